// round 10
// baseline (speedup 1.0000x reference)
#include <cuda_runtime.h>
#include <cuda_fp16.h>
#include <math.h>
#include <stdint.h>

// Problem constants: N=10000, E=40000, IN_CH=256, OUT_CH=256,
// EDGE_DIM=128, NS=64, NV=8, WN1=WN2=5120.

#define MAXN 10000
#define MAXE 40000

// ---------------- scratch (static __device__ — no allocations allowed) -----
__device__ float  g_skip[MAXN * 256];
__device__ float  g_h   [MAXN * 64];
__device__ __half g_u1h [MAXE * 128];
__device__ __half g_u2h [MAXE * 128];
__device__ float  g_shb [MAXE * 8];     // sh1 (3) + sh2 (5)
__device__ float  g_h1  [MAXN * 128];   // RAW msg1 sums (finalized inline in msg2)
__device__ float  g_cnt [MAXN];
__device__ float  g_h2  [MAXN * 64];
__device__ float  g_mu  [64];
__device__ float  g_var [64];
__device__ float  g_sph [MAXN * 64];
__device__ __half g_w1t [5120 * 128];   // fc1_w2 transposed [5120,128], fp16
__device__ __half g_w2t [5120 * 128];   // fc2_w2 transposed, fp16
__device__ __half g_wt1a[128 * 128];    // fc1_w1 transposed, fp16
__device__ __half g_wt1b[128 * 128];    // fc2_w1 transposed, fp16

__device__ __forceinline__ float softplusf(float x) {
    return fmaxf(x, 0.0f) + log1pf(expf(-fabsf(x)));
}
__device__ __forceinline__ uint32_t smem_u32(const void* p) {
    uint32_t a;
    asm("{ .reg .u64 t; cvta.to.shared.u64 t, %1; cvt.u32.u64 %0, t; }"
        : "=r"(a) : "l"(p));
    return a;
}
__device__ __forceinline__ uint32_t pack_h2(float x, float y) {
    __half2 h = __floats2half2_rn(x, y);
    return *reinterpret_cast<uint32_t*>(&h);
}
__device__ __forceinline__ void mma_f16_m16n8k16(float c[4],
    uint32_t a0, uint32_t a1, uint32_t a2, uint32_t a3,
    uint32_t b0, uint32_t b1)
{
    asm volatile(
        "mma.sync.aligned.m16n8k16.row.col.f32.f16.f16.f32 "
        "{%0,%1,%2,%3}, {%4,%5,%6,%7}, {%8,%9}, {%0,%1,%2,%3};"
        : "+f"(c[0]), "+f"(c[1]), "+f"(c[2]), "+f"(c[3])
        : "r"(a0), "r"(a1), "r"(a2), "r"(a3), "r"(b0), "r"(b1));
}
#define CP_ASYNC16(dst, src) \
    asm volatile("cp.async.cg.shared.global [%0], [%1], 16;" :: "r"(dst), "l"(src))
#define CP_COMMIT()  asm volatile("cp.async.commit_group;" ::: "memory")
#define CP_WAIT0()   asm volatile("cp.async.wait_group 0;" ::: "memory")

// ======================= generic fp32 GEMM (small mats) =====================
template <int ACT, int ADD>
__global__ void __launch_bounds__(256) gemm_kernel(
    const float* __restrict__ A, const float* __restrict__ B,
    const float* __restrict__ bias, const float* __restrict__ addsrc,
    float* __restrict__ C, int M, int N, int K)
{
    __shared__ float As[16][64];
    __shared__ float Bs[16][64];
    const int bm = blockIdx.y * 64, bn = blockIdx.x * 64;
    const int tid = threadIdx.x;
    const int ty = tid >> 4, tx = tid & 15;

    float acc[4][4] = {};
    for (int k0 = 0; k0 < K; k0 += 16) {
#pragma unroll
        for (int l = 0; l < 4; ++l) {
            int idx = tid + l * 256;
            int r = idx >> 4, c = idx & 15;
            int gr = bm + r;
            As[c][r] = (gr < M) ? A[(size_t)gr * K + k0 + c] : 0.0f;
        }
#pragma unroll
        for (int l = 0; l < 4; ++l) {
            int idx = tid + l * 256;
            int r = idx >> 6, c = idx & 63;
            Bs[r][c] = B[(size_t)(k0 + r) * N + bn + c];
        }
        __syncthreads();
#pragma unroll
        for (int kk = 0; kk < 16; ++kk) {
            float ra[4], rb[4];
#pragma unroll
            for (int a = 0; a < 4; ++a) ra[a] = As[kk][ty * 4 + a];
#pragma unroll
            for (int b = 0; b < 4; ++b) rb[b] = Bs[kk][tx * 4 + b];
#pragma unroll
            for (int a = 0; a < 4; ++a)
#pragma unroll
                for (int b = 0; b < 4; ++b)
                    acc[a][b] = fmaf(ra[a], rb[b], acc[a][b]);
        }
        __syncthreads();
    }
#pragma unroll
    for (int a = 0; a < 4; ++a) {
        int m = bm + ty * 4 + a;
        if (m >= M) continue;
#pragma unroll
        for (int b = 0; b < 4; ++b) {
            int n = bn + tx * 4 + b;
            float v = acc[a][b] + bias[n];
            if (ACT) v = softplusf(v);
            if (ADD) v += addsrc[(size_t)m * N + n];
            C[(size_t)m * N + n] = v;
        }
    }
}

// ---- weight transpose [128,5120] -> [5120,128], converted to fp16 ---------
__global__ void transpose_kernel(const float* __restrict__ W, __half* __restrict__ WT)
{
    __shared__ float t[32][33];
    const int j0 = blockIdx.x * 32, d0 = blockIdx.y * 32;
    for (int r = threadIdx.y; r < 32; r += 8)
        t[r][threadIdx.x] = W[(size_t)(d0 + r) * 5120 + j0 + threadIdx.x];
    __syncthreads();
    for (int r = threadIdx.y; r < 32; r += 8)
        WT[(size_t)(j0 + r) * 128 + d0 + threadIdx.x] =
            __float2half_rn(t[threadIdx.x][r]);
}

// ---- transpose [128,128] fp32 -> fp16 --------------------------------------
__global__ void transpose128_kernel(const float* __restrict__ W, __half* __restrict__ WT)
{
    __shared__ float t[32][33];
    const int n0 = blockIdx.x * 32, k0 = blockIdx.y * 32;
    for (int r = threadIdx.y; r < 32; r += 8)
        t[r][threadIdx.x] = W[(size_t)(k0 + r) * 128 + n0 + threadIdx.x];
    __syncthreads();
    for (int r = threadIdx.y; r < 32; r += 8)
        WT[(size_t)(n0 + r) * 128 + k0 + threadIdx.x] =
            __float2half_rn(t[threadIdx.x][r]);
}

// ---------------- fused prep: spherical harmonics + zeroing -----------------
__global__ void prep_kernel(const float* __restrict__ ev, int E, int Nn)
{
    int t = blockIdx.x * blockDim.x + threadIdx.x;
    int gs = gridDim.x * blockDim.x;
    for (int e = t; e < E; e += gs) {
        float x = ev[e * 3 + 0], y = ev[e * 3 + 1], z = ev[e * 3 + 2];
        float rn = rsqrtf(x * x + y * y + z * z);
        x *= rn; y *= rn; z *= rn;
        const float s3 = 1.7320508075688772f;
        const float s5 = 2.2360679774997896f;
        float* o = g_shb + (size_t)e * 8;
        o[0] = s3 * x;
        o[1] = s3 * y;
        o[2] = s3 * z;
        o[3] = s5 * s3 * x * z;
        o[4] = s5 * s3 * x * y;
        o[5] = s5 * (y * y - 0.5f * (x * x + z * z));
        o[6] = s5 * s3 * y * z;
        o[7] = s5 * (s3 * 0.5f) * (z * z - x * x);
    }
    for (int i = t; i < Nn * 128; i += gs) g_h1[i] = 0.0f;
    for (int i = t; i < Nn * 64;  i += gs) g_h2[i] = 0.0f;
    for (int i = t; i < Nn;       i += gs) g_cnt[i] = 0.0f;
}

// ======================= fp16 MMA first-layer GEMM ==========================
// Out[M,128] = softplus(A[M,128] @ WT^T + bias), fp16 out. 512 thr, 16 warps:
// warp = (mt = wid>>1 rows, nh = wid&1 col-half). A fp32->fp16 to registers,
// W fp16 XOR-swizzled smem via cp.async.
__global__ void __launch_bounds__(512) ugemm_kernel(
    const float* __restrict__ A, const __half* __restrict__ WT,
    const float* __restrict__ bias, __half* __restrict__ Out, int M)
{
    __shared__ __align__(16) char ws[32768];
    const int tid = threadIdx.x;
    const int wid = tid >> 5, lane = tid & 31;
    const int mt = wid >> 1, nh = wid & 1;
    const int lq = lane >> 2, la = lane & 3;

    for (int idx = tid; idx < 2048; idx += 512) {
        int row = idx >> 4, q = idx & 15;
        const __half* src = WT + (size_t)row * 128 + q * 8;
        uint32_t dst = smem_u32(ws + row * 256 + ((q ^ (row & 7)) * 16));
        CP_ASYNC16(dst, src);
    }
    CP_COMMIT();

    const int r0 = blockIdx.x * 128 + mt * 16 + lq;
    const int r1 = r0 + 8;
    const bool v0 = r0 < M, v1 = r1 < M;

    uint32_t A0[8], A1[8], A2[8], A3[8];
    {
        const float* a0p = A + (size_t)(v0 ? r0 : 0) * 128 + 2 * la;
        const float* a1p = A + (size_t)(v1 ? r1 : 0) * 128 + 2 * la;
#pragma unroll
        for (int ks = 0; ks < 8; ++ks) {
            float2 f0 = *reinterpret_cast<const float2*>(a0p + ks * 16);
            float2 f2 = *reinterpret_cast<const float2*>(a0p + ks * 16 + 8);
            float2 f1 = *reinterpret_cast<const float2*>(a1p + ks * 16);
            float2 f3 = *reinterpret_cast<const float2*>(a1p + ks * 16 + 8);
            A0[ks] = v0 ? pack_h2(f0.x, f0.y) : 0u;
            A2[ks] = v0 ? pack_h2(f2.x, f2.y) : 0u;
            A1[ks] = v1 ? pack_h2(f1.x, f1.y) : 0u;
            A3[ks] = v1 ? pack_h2(f3.x, f3.y) : 0u;
        }
    }

    float c[8][4];
#pragma unroll
    for (int nt = 0; nt < 8; ++nt) {
        float2 bb = __ldg(reinterpret_cast<const float2*>(
            bias + (nh * 8 + nt) * 8 + la * 2));
        c[nt][0] = bb.x; c[nt][1] = bb.y;
        c[nt][2] = bb.x; c[nt][3] = bb.y;
    }

    CP_WAIT0();
    __syncthreads();
    const uint32_t* wb = reinterpret_cast<const uint32_t*>(ws);
#pragma unroll
    for (int ks = 0; ks < 8; ++ks) {
#pragma unroll
        for (int nt = 0; nt < 8; ++nt) {
            const int nrow = (nh * 8 + nt) * 8 + lq;
            const int base = nrow * 64;
            uint32_t b0 = wb[base + (((2 * ks)     ^ lq) * 4) + la];
            uint32_t b1 = wb[base + (((2 * ks + 1) ^ lq) * 4) + la];
            mma_f16_m16n8k16(c[nt], A0[ks], A1[ks], A2[ks], A3[ks], b0, b1);
        }
    }

#pragma unroll
    for (int nt = 0; nt < 8; ++nt) {
        int col = (nh * 8 + nt) * 8 + la * 2;
        if (v0) {
            __half2 h = __floats2half2_rn(softplusf(c[nt][0]), softplusf(c[nt][1]));
            *reinterpret_cast<__half2*>(Out + (size_t)r0 * 128 + col) = h;
        }
        if (v1) {
            __half2 h = __floats2half2_rn(softplusf(c[nt][2]), softplusf(c[nt][3]));
            *reinterpret_cast<__half2*>(Out + (size_t)r1 * 128 + col) = h;
        }
    }
}

// ======================= fp16 mma.sync fused message pass ====================
// 64 edges/CTA, 256 threads, 8 warps, 2 CTAs/SM. 40 chunk-pairs with cp.async
// double buffering. Bias via __ldg (L1-resident). PASS2 finalizes h1 inline
// (divide by cnt, add self term).
//
// smem bytes: sW0 @0 (32768 = pair of chunks), sW1 @32768, sS @65536 (64x81).
#define EBLK     64
#define MSG_NTHR 256
#define OFF_W0   0
#define OFF_W1   32768
#define OFF_SS   65536
#define SMEM_MSG_B (65536 + EBLK * 81 * 4)   // 86272

__device__ __forceinline__ void fill_W2_async(char* smem, uint32_t bufoff,
    const __half* __restrict__ WT, int ch0, int tid)
{
    for (int idx = tid; idx < 2048; idx += MSG_NTHR) {
        int sub = idx >> 10;
        int w   = idx & 1023;
        int row = w >> 4;
        int q   = w & 15;
        const __half* src = WT + ((size_t)(ch0 + sub) * 64 + row) * 128 + q * 8;
        uint32_t dst = smem_u32(smem + bufoff + sub * 16384 +
                                row * 256 + ((q ^ (row & 7)) * 16));
        CP_ASYNC16(dst, src);
    }
}

template <int PASS>
__global__ void __launch_bounds__(MSG_NTHR, 2) msg_mma_kernel(
    const int* __restrict__ ei, const __half* __restrict__ Uh,
    const __half* __restrict__ WT, const float* __restrict__ B2, int E)
{
    extern __shared__ __align__(16) char smem[];
    float* sS = reinterpret_cast<float*>(smem + OFF_SS);   // [64][81]

    const int tid = threadIdx.x;
    const int wid = tid >> 5, lane = tid & 31;
    const int mt = wid >> 1, nh = wid & 1;
    const int lq = lane >> 2, la = lane & 3;
    const int e0 = blockIdx.x * EBLK;
    const int ne = min(EBLK, E - e0);
    const int r0 = mt * 16 + lq, r1 = r0 + 8;
    const bool v0 = r0 < ne, v1 = r1 < ne;

    fill_W2_async(smem, OFF_W0, WT, 0, tid);
    CP_COMMIT();

    // ---- S tile ----
    if (PASS == 1) {
        for (int idx = tid; idx < EBLK * 64; idx += MSG_NTHR) {
            int e = idx >> 6, i = idx & 63;
            float v = 0.0f;
            if (e < ne) {
                int dst = ei[E + e0 + e];
                v = g_h[(size_t)dst * 64 + i];
            }
            sS[e * 81 + i] = v;
        }
    } else {
        // inline h1 finalize: h1fin = raw/cnt (+ h for scalar part)
        for (int idx = tid; idx < EBLK * 80; idx += MSG_NTHR) {
            int e = idx / 80, j = idx - e * 80;
            float v = 0.0f;
            if (e < ne) {
                int dst = ei[E + e0 + e];
                float rc = 1.0f / fmaxf(g_cnt[dst], 1.0f);
                const float* he = g_h1 + (size_t)dst * 128;
                if (j < 64) {
                    v = he[j] * rc + g_h[(size_t)dst * 64 + j];
                } else if (j < 72) {
                    int i = j - 64; float p = 0.0f;
#pragma unroll
                    for (int m = 0; m < 3; ++m)
                        p += he[64 + i * 3 + m] * g_shb[(size_t)(e0 + e) * 8 + m];
                    v = p * rc * 0.5773502691896258f;
                } else {
                    int i = j - 72; float p = 0.0f;
#pragma unroll
                    for (int m = 0; m < 5; ++m)
                        p += he[88 + i * 5 + m] * g_shb[(size_t)(e0 + e) * 8 + 3 + m];
                    v = p * rc * 0.4472135954999579f;
                }
            }
            sS[e * 81 + j] = v;
        }
    }

    // ---- A registers: U rows r0, r1 as half2 ----
    uint32_t A0[8], A1[8], A2[8], A3[8];
    {
        const uint32_t* u0 = reinterpret_cast<const uint32_t*>(
            Uh + (size_t)(e0 + (v0 ? r0 : 0)) * 128) + la;
        const uint32_t* u1 = reinterpret_cast<const uint32_t*>(
            Uh + (size_t)(e0 + (v1 ? r1 : 0)) * 128) + la;
#pragma unroll
        for (int ks = 0; ks < 8; ++ks) {
            A0[ks] = v0 ? u0[ks * 8]     : 0u;
            A2[ks] = v0 ? u0[ks * 8 + 4] : 0u;
            A1[ks] = v1 ? u1[ks * 8]     : 0u;
            A3[ks] = v1 ? u1[ks * 8 + 4] : 0u;
        }
    }

    float accA[4][4];
    float accB[4], accC[4];
#pragma unroll
    for (int i = 0; i < 4; ++i) {
#pragma unroll
        for (int j = 0; j < 4; ++j) accA[i][j] = 0.0f;
        accB[i] = 0.0f; accC[i] = 0.0f;
    }

    CP_WAIT0();
    __syncthreads();

    for (int cp = 0; cp < 40; ++cp) {
        const char* cur = smem + ((cp & 1) ? OFF_W1 : OFF_W0);
        if (cp + 1 < 40) {
            fill_W2_async(smem, (cp & 1) ? OFF_W0 : OFF_W1, WT, 2 * (cp + 1), tid);
            CP_COMMIT();
        }

#pragma unroll
        for (int sub = 0; sub < 2; ++sub) {
            const int ch = 2 * cp + sub;
            const uint32_t* wb = reinterpret_cast<const uint32_t*>(cur + sub * 16384);

            float c[4][4];
#pragma unroll
            for (int ntl = 0; ntl < 4; ++ntl) {
                float2 bb = __ldg(reinterpret_cast<const float2*>(
                    B2 + ch * 64 + (nh * 4 + ntl) * 8 + la * 2));
                c[ntl][0] = bb.x; c[ntl][1] = bb.y;
                c[ntl][2] = bb.x; c[ntl][3] = bb.y;
            }

#pragma unroll
            for (int ks = 0; ks < 8; ++ks) {
#pragma unroll
                for (int ntl = 0; ntl < 4; ++ntl) {
                    const int nrow = (nh * 4 + ntl) * 8 + lq;
                    const int base = nrow * 64;
                    uint32_t b0 = wb[base + (((2 * ks)     ^ lq) * 4) + la];
                    uint32_t b1 = wb[base + (((2 * ks + 1) ^ lq) * 4) + la];
                    mma_f16_m16n8k16(c[ntl], A0[ks], A1[ks], A2[ks], A3[ks], b0, b1);
                }
            }

            if (PASS == 2 || ch < 64) {
                float s0 = sS[r0 * 81 + ch];
                float s1 = sS[r1 * 81 + ch];
#pragma unroll
                for (int ntl = 0; ntl < 4; ++ntl) {
                    accA[ntl][0] = fmaf(s0, c[ntl][0], accA[ntl][0]);
                    accA[ntl][1] = fmaf(s0, c[ntl][1], accA[ntl][1]);
                    accA[ntl][2] = fmaf(s1, c[ntl][2], accA[ntl][2]);
                    accA[ntl][3] = fmaf(s1, c[ntl][3], accA[ntl][3]);
                }
            } else if (ch < 72) {
#pragma unroll
                for (int ntl = 0; ntl < 4; ++ntl) {
                    int i = (ch - 64) * 8 + nh * 4 + ntl;
                    float s0 = sS[r0 * 81 + i];
                    float s1 = sS[r1 * 81 + i];
                    accB[0] = fmaf(s0, c[ntl][0], accB[0]);
                    accB[1] = fmaf(s0, c[ntl][1], accB[1]);
                    accB[2] = fmaf(s1, c[ntl][2], accB[2]);
                    accB[3] = fmaf(s1, c[ntl][3], accB[3]);
                }
            } else {
#pragma unroll
                for (int ntl = 0; ntl < 4; ++ntl) {
                    int i = (ch - 72) * 8 + nh * 4 + ntl;
                    float s0 = sS[r0 * 81 + i];
                    float s1 = sS[r1 * 81 + i];
                    accC[0] = fmaf(s0, c[ntl][0], accC[0]);
                    accC[1] = fmaf(s0, c[ntl][1], accC[1]);
                    accC[2] = fmaf(s1, c[ntl][2], accC[2]);
                    accC[3] = fmaf(s1, c[ntl][3], accC[3]);
                }
            }
        }

        if (cp + 1 < 40) CP_WAIT0();
        __syncthreads();
    }

    // ---- epilogue scatter ----
#pragma unroll
    for (int e = 0; e < 2; ++e) {
        int r = e ? r1 : r0;
        if (r >= ne) continue;
        int src = ei[e0 + r];
        if (PASS == 1) {
            const float C1 = 0.125f;
            float* d1 = g_h1 + (size_t)src * 128;
#pragma unroll
            for (int ntl = 0; ntl < 4; ++ntl) {
                int col = (nh * 4 + ntl) * 8 + la * 2;
                atomicAdd(d1 + col,     C1 * accA[ntl][e * 2]);
                atomicAdd(d1 + col + 1, C1 * accA[ntl][e * 2 + 1]);
            }
            float sh[8];
#pragma unroll
            for (int m = 0; m < 8; ++m) sh[m] = g_shb[(size_t)(e0 + r) * 8 + m];
#pragma unroll
            for (int b = 0; b < 2; ++b) {
                int k = la * 2 + b;
                float a1v = C1 * accB[e * 2 + b];
                float a2v = C1 * accC[e * 2 + b];
#pragma unroll
                for (int m = 0; m < 3; ++m)
                    atomicAdd(d1 + 64 + k * 3 + m, a1v * sh[m]);
#pragma unroll
                for (int m = 0; m < 5; ++m)
                    atomicAdd(d1 + 88 + k * 5 + m, a2v * sh[3 + m]);
            }
            if (nh == 0 && la == 0) atomicAdd(&g_cnt[src], 1.0f);
        } else {
            const float INV = 0.11180339887498948f;  // 1/sqrt(80)
            float* d2 = g_h2 + (size_t)src * 64;
#pragma unroll
            for (int ntl = 0; ntl < 4; ++ntl) {
                int col = (nh * 4 + ntl) * 8 + la * 2;
                atomicAdd(d2 + col,     INV * accA[ntl][e * 2]);
                atomicAdd(d2 + col + 1, INV * accA[ntl][e * 2 + 1]);
            }
        }
    }
}

// ---------------- fused h2 finalize + batch-norm stats ----------------------
__global__ void bn_stats_kernel(int Nn)
{
    __shared__ float rs[256], rs2[256];
    const int c = blockIdx.x;
    float s = 0.0f, s2 = 0.0f;
    for (int n = threadIdx.x; n < Nn; n += 256) {
        float x = g_h2[(size_t)n * 64 + c] / fmaxf(g_cnt[n], 1.0f);
        g_h2[(size_t)n * 64 + c] = x;
        s += x; s2 += x * x;
    }
    rs[threadIdx.x] = s; rs2[threadIdx.x] = s2;
    __syncthreads();
    for (int off = 128; off > 0; off >>= 1) {
        if (threadIdx.x < off) {
            rs[threadIdx.x]  += rs[threadIdx.x + off];
            rs2[threadIdx.x] += rs2[threadIdx.x + off];
        }
        __syncthreads();
    }
    if (threadIdx.x == 0) {
        float mu = rs[0] / (float)Nn;
        g_mu[c]  = mu;
        g_var[c] = rs2[0] / (float)Nn - mu * mu;
    }
}

__global__ void bn_apply_kernel(const float* __restrict__ gamma,
                                const float* __restrict__ beta, int Nn)
{
    int t = blockIdx.x * blockDim.x + threadIdx.x;
    int gs = gridDim.x * blockDim.x;
    for (int idx = t; idx < Nn * 64; idx += gs) {
        int c = idx & 63;
        float x = (g_h2[idx] - g_mu[c]) * rsqrtf(g_var[c] + 1e-5f) * gamma[c] + beta[c];
        g_sph[idx] = softplusf(x);
    }
}

// ---------------- launch ----------------------------------------------------
extern "C" void kernel_launch(void* const* d_in, const int* in_sizes, int n_in,
                              void* d_out, int out_size)
{
    const float* node_feature = (const float*)d_in[0];
    const int*   edge_index   = (const int*)d_in[1];
    const float* edge_feature = (const float*)d_in[2];
    const float* edge_vec     = (const float*)d_in[3];
    const float* w_node = (const float*)d_in[4];
    const float* b_node = (const float*)d_in[5];
    const float* w_skip = (const float*)d_in[6];
    const float* b_skip = (const float*)d_in[7];
    const float* fc1_w1 = (const float*)d_in[8];
    const float* fc1_b1 = (const float*)d_in[9];
    const float* fc1_w2 = (const float*)d_in[10];
    const float* fc1_b2 = (const float*)d_in[11];
    const float* fc2_w1 = (const float*)d_in[12];
    const float* fc2_b1 = (const float*)d_in[13];
    const float* fc2_w2 = (const float*)d_in[14];
    const float* fc2_b2 = (const float*)d_in[15];
    const float* bn_gamma = (const float*)d_in[16];
    const float* bn_beta  = (const float*)d_in[17];
    const float* w_out = (const float*)d_in[18];
    const float* b_out = (const float*)d_in[19];
    float* out = (float*)d_out;

    const int Nn = in_sizes[0] / 256;   // 10000
    const int E  = in_sizes[2] / 128;   // 40000

    float *p_skip, *p_h, *p_sph;
    __half *p_u1h, *p_u2h, *p_w1t, *p_w2t, *p_wt1a, *p_wt1b;
    cudaGetSymbolAddress((void**)&p_skip, g_skip);
    cudaGetSymbolAddress((void**)&p_h,    g_h);
    cudaGetSymbolAddress((void**)&p_u1h,  g_u1h);
    cudaGetSymbolAddress((void**)&p_u2h,  g_u2h);
    cudaGetSymbolAddress((void**)&p_sph,  g_sph);
    cudaGetSymbolAddress((void**)&p_w1t,  g_w1t);
    cudaGetSymbolAddress((void**)&p_w2t,  g_w2t);
    cudaGetSymbolAddress((void**)&p_wt1a, g_wt1a);
    cudaGetSymbolAddress((void**)&p_wt1b, g_wt1b);

    cudaFuncSetAttribute((const void*)msg_mma_kernel<1>,
                         cudaFuncAttributeMaxDynamicSharedMemorySize, SMEM_MSG_B);
    cudaFuncSetAttribute((const void*)msg_mma_kernel<2>,
                         cudaFuncAttributeMaxDynamicSharedMemorySize, SMEM_MSG_B);

    // weight transposes (fp16) + fused sh/zero prep
    transpose_kernel<<<dim3(160, 4), dim3(32, 8)>>>(fc1_w2, p_w1t);
    transpose_kernel<<<dim3(160, 4), dim3(32, 8)>>>(fc2_w2, p_w2t);
    transpose128_kernel<<<dim3(4, 4), dim3(32, 8)>>>(fc1_w1, p_wt1a);
    transpose128_kernel<<<dim3(4, 4), dim3(32, 8)>>>(fc2_w1, p_wt1b);
    prep_kernel<<<256, 256>>>(edge_vec, E, Nn);

    // node-side GEMMs (fp32 out, scalar)
    gemm_kernel<0, 0><<<dim3(4, (Nn + 63) / 64), 256>>>(
        node_feature, w_skip, b_skip, nullptr, p_skip, Nn, 256, 256);
    gemm_kernel<0, 0><<<dim3(1, (Nn + 63) / 64), 256>>>(
        node_feature, w_node, b_node, nullptr, p_h, Nn, 64, 256);

    // edge MLP first layers via fp16 MMA (softplus, fp16 out)
    const int ublk = (E + 127) / 128;
    ugemm_kernel<<<ublk, 512>>>(edge_feature, p_wt1a, fc1_b1, p_u1h, E);
    ugemm_kernel<<<ublk, 512>>>(edge_feature, p_wt1b, fc2_b1, p_u2h, E);

    const int nblk = (E + EBLK - 1) / EBLK;
    msg_mma_kernel<1><<<nblk, MSG_NTHR, SMEM_MSG_B>>>(edge_index, p_u1h, p_w1t, fc1_b2, E);
    msg_mma_kernel<2><<<nblk, MSG_NTHR, SMEM_MSG_B>>>(edge_index, p_u2h, p_w2t, fc2_b2, E);

    bn_stats_kernel<<<64, 256>>>(Nn);
    bn_apply_kernel<<<256, 256>>>(bn_gamma, bn_beta, Nn);

    // out = softplus(sph @ w_out + b_out) + skip
    gemm_kernel<1, 1><<<dim3(4, (Nn + 63) / 64), 256>>>(
        p_sph, w_out, b_out, p_skip, out, Nn, 256, 64);
}

// round 11
// speedup vs baseline: 1.5094x; 1.5094x over previous
#include <cuda_runtime.h>
#include <cuda_fp16.h>
#include <math.h>
#include <stdint.h>

// Problem constants: N=10000, E=40000, IN_CH=256, OUT_CH=256,
// EDGE_DIM=128, NS=64, NV=8, WN1=WN2=5120.

#define MAXN 10000
#define MAXE 40000

// ---------------- scratch (static __device__ — no allocations allowed) -----
__device__ float  g_skip[MAXN * 256];
__device__ float  g_h   [MAXN * 64];
__device__ __half g_u1h [MAXE * 128];
__device__ __half g_u2h [MAXE * 128];
__device__ float  g_shb [MAXE * 8];     // sh1 (3) + sh2 (5)
__device__ float  g_h1  [MAXN * 128];   // RAW msg1 sums (finalized inline in msg2)
__device__ float  g_cnt [MAXN];
__device__ float  g_h2  [MAXN * 64];
__device__ float  g_mu  [64];
__device__ float  g_var [64];
__device__ float  g_sph [MAXN * 64];
__device__ __half g_w1t [5120 * 128];   // fc1_w2 transposed [5120,128], fp16
__device__ __half g_w2t [5120 * 128];   // fc2_w2 transposed, fp16
__device__ __half g_wt1a[128 * 128];    // fc1_w1 transposed, fp16
__device__ __half g_wt1b[128 * 128];    // fc2_w1 transposed, fp16

__device__ __forceinline__ float softplusf(float x) {
    return fmaxf(x, 0.0f) + log1pf(expf(-fabsf(x)));
}
__device__ __forceinline__ uint32_t smem_u32(const void* p) {
    uint32_t a;
    asm("{ .reg .u64 t; cvta.to.shared.u64 t, %1; cvt.u32.u64 %0, t; }"
        : "=r"(a) : "l"(p));
    return a;
}
__device__ __forceinline__ uint32_t pack_h2(float x, float y) {
    __half2 h = __floats2half2_rn(x, y);
    return *reinterpret_cast<uint32_t*>(&h);
}
__device__ __forceinline__ void mma_f16_m16n8k16(float c[4],
    uint32_t a0, uint32_t a1, uint32_t a2, uint32_t a3,
    uint32_t b0, uint32_t b1)
{
    asm volatile(
        "mma.sync.aligned.m16n8k16.row.col.f32.f16.f16.f32 "
        "{%0,%1,%2,%3}, {%4,%5,%6,%7}, {%8,%9}, {%0,%1,%2,%3};"
        : "+f"(c[0]), "+f"(c[1]), "+f"(c[2]), "+f"(c[3])
        : "r"(a0), "r"(a1), "r"(a2), "r"(a3), "r"(b0), "r"(b1));
}
#define CP_ASYNC16(dst, src) \
    asm volatile("cp.async.cg.shared.global [%0], [%1], 16;" :: "r"(dst), "l"(src))
#define CP_COMMIT()  asm volatile("cp.async.commit_group;" ::: "memory")
#define CP_WAIT0()   asm volatile("cp.async.wait_group 0;" ::: "memory")

// ======================= generic fp32 GEMM (small mats) =====================
template <int ACT, int ADD>
__global__ void __launch_bounds__(256) gemm_kernel(
    const float* __restrict__ A, const float* __restrict__ B,
    const float* __restrict__ bias, const float* __restrict__ addsrc,
    float* __restrict__ C, int M, int N, int K)
{
    __shared__ float As[16][64];
    __shared__ float Bs[16][64];
    const int bm = blockIdx.y * 64, bn = blockIdx.x * 64;
    const int tid = threadIdx.x;
    const int ty = tid >> 4, tx = tid & 15;

    float acc[4][4] = {};
    for (int k0 = 0; k0 < K; k0 += 16) {
#pragma unroll
        for (int l = 0; l < 4; ++l) {
            int idx = tid + l * 256;
            int r = idx >> 4, c = idx & 15;
            int gr = bm + r;
            As[c][r] = (gr < M) ? A[(size_t)gr * K + k0 + c] : 0.0f;
        }
#pragma unroll
        for (int l = 0; l < 4; ++l) {
            int idx = tid + l * 256;
            int r = idx >> 6, c = idx & 63;
            Bs[r][c] = B[(size_t)(k0 + r) * N + bn + c];
        }
        __syncthreads();
#pragma unroll
        for (int kk = 0; kk < 16; ++kk) {
            float ra[4], rb[4];
#pragma unroll
            for (int a = 0; a < 4; ++a) ra[a] = As[kk][ty * 4 + a];
#pragma unroll
            for (int b = 0; b < 4; ++b) rb[b] = Bs[kk][tx * 4 + b];
#pragma unroll
            for (int a = 0; a < 4; ++a)
#pragma unroll
                for (int b = 0; b < 4; ++b)
                    acc[a][b] = fmaf(ra[a], rb[b], acc[a][b]);
        }
        __syncthreads();
    }
#pragma unroll
    for (int a = 0; a < 4; ++a) {
        int m = bm + ty * 4 + a;
        if (m >= M) continue;
#pragma unroll
        for (int b = 0; b < 4; ++b) {
            int n = bn + tx * 4 + b;
            float v = acc[a][b] + bias[n];
            if (ACT) v = softplusf(v);
            if (ADD) v += addsrc[(size_t)m * N + n];
            C[(size_t)m * N + n] = v;
        }
    }
}

// ---- weight transpose [128,5120] -> [5120,128], converted to fp16 ---------
__global__ void transpose_kernel(const float* __restrict__ W, __half* __restrict__ WT)
{
    __shared__ float t[32][33];
    const int j0 = blockIdx.x * 32, d0 = blockIdx.y * 32;
    for (int r = threadIdx.y; r < 32; r += 8)
        t[r][threadIdx.x] = W[(size_t)(d0 + r) * 5120 + j0 + threadIdx.x];
    __syncthreads();
    for (int r = threadIdx.y; r < 32; r += 8)
        WT[(size_t)(j0 + r) * 128 + d0 + threadIdx.x] =
            __float2half_rn(t[threadIdx.x][r]);
}

// ---- transpose [128,128] fp32 -> fp16 --------------------------------------
__global__ void transpose128_kernel(const float* __restrict__ W, __half* __restrict__ WT)
{
    __shared__ float t[32][33];
    const int n0 = blockIdx.x * 32, k0 = blockIdx.y * 32;
    for (int r = threadIdx.y; r < 32; r += 8)
        t[r][threadIdx.x] = W[(size_t)(k0 + r) * 128 + n0 + threadIdx.x];
    __syncthreads();
    for (int r = threadIdx.y; r < 32; r += 8)
        WT[(size_t)(n0 + r) * 128 + k0 + threadIdx.x] =
            __float2half_rn(t[threadIdx.x][r]);
}

// ---------------- fused prep: spherical harmonics + zeroing -----------------
__global__ void prep_kernel(const float* __restrict__ ev, int E, int Nn)
{
    int t = blockIdx.x * blockDim.x + threadIdx.x;
    int gs = gridDim.x * blockDim.x;
    for (int e = t; e < E; e += gs) {
        float x = ev[e * 3 + 0], y = ev[e * 3 + 1], z = ev[e * 3 + 2];
        float rn = rsqrtf(x * x + y * y + z * z);
        x *= rn; y *= rn; z *= rn;
        const float s3 = 1.7320508075688772f;
        const float s5 = 2.2360679774997896f;
        float* o = g_shb + (size_t)e * 8;
        o[0] = s3 * x;
        o[1] = s3 * y;
        o[2] = s3 * z;
        o[3] = s5 * s3 * x * z;
        o[4] = s5 * s3 * x * y;
        o[5] = s5 * (y * y - 0.5f * (x * x + z * z));
        o[6] = s5 * s3 * y * z;
        o[7] = s5 * (s3 * 0.5f) * (z * z - x * x);
    }
    for (int i = t; i < Nn * 128; i += gs) g_h1[i] = 0.0f;
    for (int i = t; i < Nn * 64;  i += gs) g_h2[i] = 0.0f;
    for (int i = t; i < Nn;       i += gs) g_cnt[i] = 0.0f;
}

// ======================= fp16 MMA first-layer GEMM ==========================
// Out[M,128] = softplus(A[M,128] @ WT^T + bias), fp16 out. 512 thr, 16 warps.
__global__ void __launch_bounds__(512) ugemm_kernel(
    const float* __restrict__ A, const __half* __restrict__ WT,
    const float* __restrict__ bias, __half* __restrict__ Out, int M)
{
    __shared__ __align__(16) char ws[32768];
    const int tid = threadIdx.x;
    const int wid = tid >> 5, lane = tid & 31;
    const int mt = wid >> 1, nh = wid & 1;
    const int lq = lane >> 2, la = lane & 3;

    for (int idx = tid; idx < 2048; idx += 512) {
        int row = idx >> 4, q = idx & 15;
        const __half* src = WT + (size_t)row * 128 + q * 8;
        uint32_t dst = smem_u32(ws + row * 256 + ((q ^ (row & 7)) * 16));
        CP_ASYNC16(dst, src);
    }
    CP_COMMIT();

    const int r0 = blockIdx.x * 128 + mt * 16 + lq;
    const int r1 = r0 + 8;
    const bool v0 = r0 < M, v1 = r1 < M;

    uint32_t A0[8], A1[8], A2[8], A3[8];
    {
        const float* a0p = A + (size_t)(v0 ? r0 : 0) * 128 + 2 * la;
        const float* a1p = A + (size_t)(v1 ? r1 : 0) * 128 + 2 * la;
#pragma unroll
        for (int ks = 0; ks < 8; ++ks) {
            float2 f0 = *reinterpret_cast<const float2*>(a0p + ks * 16);
            float2 f2 = *reinterpret_cast<const float2*>(a0p + ks * 16 + 8);
            float2 f1 = *reinterpret_cast<const float2*>(a1p + ks * 16);
            float2 f3 = *reinterpret_cast<const float2*>(a1p + ks * 16 + 8);
            A0[ks] = v0 ? pack_h2(f0.x, f0.y) : 0u;
            A2[ks] = v0 ? pack_h2(f2.x, f2.y) : 0u;
            A1[ks] = v1 ? pack_h2(f1.x, f1.y) : 0u;
            A3[ks] = v1 ? pack_h2(f3.x, f3.y) : 0u;
        }
    }

    float c[8][4];
#pragma unroll
    for (int nt = 0; nt < 8; ++nt) {
        float2 bb = __ldg(reinterpret_cast<const float2*>(
            bias + (nh * 8 + nt) * 8 + la * 2));
        c[nt][0] = bb.x; c[nt][1] = bb.y;
        c[nt][2] = bb.x; c[nt][3] = bb.y;
    }

    CP_WAIT0();
    __syncthreads();
    const uint32_t* wb = reinterpret_cast<const uint32_t*>(ws);
#pragma unroll
    for (int ks = 0; ks < 8; ++ks) {
#pragma unroll
        for (int nt = 0; nt < 8; ++nt) {
            const int nrow = (nh * 8 + nt) * 8 + lq;
            const int base = nrow * 64;
            uint32_t b0 = wb[base + (((2 * ks)     ^ lq) * 4) + la];
            uint32_t b1 = wb[base + (((2 * ks + 1) ^ lq) * 4) + la];
            mma_f16_m16n8k16(c[nt], A0[ks], A1[ks], A2[ks], A3[ks], b0, b1);
        }
    }

#pragma unroll
    for (int nt = 0; nt < 8; ++nt) {
        int col = (nh * 8 + nt) * 8 + la * 2;
        if (v0) {
            __half2 h = __floats2half2_rn(softplusf(c[nt][0]), softplusf(c[nt][1]));
            *reinterpret_cast<__half2*>(Out + (size_t)r0 * 128 + col) = h;
        }
        if (v1) {
            __half2 h = __floats2half2_rn(softplusf(c[nt][2]), softplusf(c[nt][3]));
            *reinterpret_cast<__half2*>(Out + (size_t)r1 * 128 + col) = h;
        }
    }
}

// ======================= fp16 mma.sync fused message pass ====================
// R9-proven shape: 96 edges/CTA, 384 threads, 12 warps, 1 CTA/SM, 40 chunk-
// pairs with cp.async double buffering, bias staged in smem. PASS2 finalizes
// h1 inline (divide by cnt, add self term) while building S.
//
// smem bytes: sW0 @0 (32768 = 2 chunks), sW1 @32768 (32768),
//             sS @65536 (96x81 fp32 = 31104), sBias @96640 (20480).
#define EBLK     96
#define NTHR     384
#define OFF_W0   0
#define OFF_W1   32768
#define OFF_SS   65536
#define OFF_BIAS 96640
#define SMEM_MSG_B 117120

__device__ __forceinline__ void fill_W2_async(char* smem, uint32_t bufoff,
    const __half* __restrict__ WT, int ch0, int tid)
{
    for (int idx = tid; idx < 2048; idx += NTHR) {
        int sub = idx >> 10;
        int w   = idx & 1023;
        int row = w >> 4;
        int q   = w & 15;
        const __half* src = WT + ((size_t)(ch0 + sub) * 64 + row) * 128 + q * 8;
        uint32_t dst = smem_u32(smem + bufoff + sub * 16384 +
                                row * 256 + ((q ^ (row & 7)) * 16));
        CP_ASYNC16(dst, src);
    }
}

template <int PASS>
__global__ void __launch_bounds__(NTHR, 1) msg_mma_kernel(
    const int* __restrict__ ei, const __half* __restrict__ Uh,
    const __half* __restrict__ WT, const float* __restrict__ B2, int E)
{
    extern __shared__ __align__(16) char smem[];
    float* sS    = reinterpret_cast<float*>(smem + OFF_SS);     // [96][81]
    float* sBias = reinterpret_cast<float*>(smem + OFF_BIAS);   // [5120]

    const int tid = threadIdx.x;
    const int wid = tid >> 5, lane = tid & 31;
    const int mt = wid >> 1, nh = wid & 1;
    const int lq = lane >> 2, la = lane & 3;
    const int e0 = blockIdx.x * EBLK;
    const int ne = min(EBLK, E - e0);
    const int r0 = mt * 16 + lq, r1 = r0 + 8;
    const bool v0 = r0 < ne, v1 = r1 < ne;

    fill_W2_async(smem, OFF_W0, WT, 0, tid);
    CP_COMMIT();

    // bias to smem
    for (int i = tid; i < 5120; i += NTHR) sBias[i] = B2[i];

    // ---- S tile ----
    if (PASS == 1) {
        for (int idx = tid; idx < EBLK * 64; idx += NTHR) {
            int e = idx >> 6, i = idx & 63;
            float v = 0.0f;
            if (e < ne) {
                int dst = ei[E + e0 + e];
                v = g_h[(size_t)dst * 64 + i];
            }
            sS[e * 81 + i] = v;
        }
    } else {
        // inline h1 finalize: h1fin = raw/cnt (+ h for scalar part)
        for (int idx = tid; idx < EBLK * 80; idx += NTHR) {
            int e = idx / 80, j = idx - e * 80;
            float v = 0.0f;
            if (e < ne) {
                int dst = ei[E + e0 + e];
                float rc = 1.0f / fmaxf(g_cnt[dst], 1.0f);
                const float* he = g_h1 + (size_t)dst * 128;
                if (j < 64) {
                    v = he[j] * rc + g_h[(size_t)dst * 64 + j];
                } else if (j < 72) {
                    int i = j - 64; float p = 0.0f;
#pragma unroll
                    for (int m = 0; m < 3; ++m)
                        p += he[64 + i * 3 + m] * g_shb[(size_t)(e0 + e) * 8 + m];
                    v = p * rc * 0.5773502691896258f;
                } else {
                    int i = j - 72; float p = 0.0f;
#pragma unroll
                    for (int m = 0; m < 5; ++m)
                        p += he[88 + i * 5 + m] * g_shb[(size_t)(e0 + e) * 8 + 3 + m];
                    v = p * rc * 0.4472135954999579f;
                }
            }
            sS[e * 81 + j] = v;
        }
    }

    // ---- A registers: U rows r0, r1 as half2 ----
    uint32_t A0[8], A1[8], A2[8], A3[8];
    {
        const uint32_t* u0 = reinterpret_cast<const uint32_t*>(
            Uh + (size_t)(e0 + (v0 ? r0 : 0)) * 128) + la;
        const uint32_t* u1 = reinterpret_cast<const uint32_t*>(
            Uh + (size_t)(e0 + (v1 ? r1 : 0)) * 128) + la;
#pragma unroll
        for (int ks = 0; ks < 8; ++ks) {
            A0[ks] = v0 ? u0[ks * 8]     : 0u;
            A2[ks] = v0 ? u0[ks * 8 + 4] : 0u;
            A1[ks] = v1 ? u1[ks * 8]     : 0u;
            A3[ks] = v1 ? u1[ks * 8 + 4] : 0u;
        }
    }

    float accA[4][4];
    float accB[4], accC[4];
#pragma unroll
    for (int i = 0; i < 4; ++i) {
#pragma unroll
        for (int j = 0; j < 4; ++j) accA[i][j] = 0.0f;
        accB[i] = 0.0f; accC[i] = 0.0f;
    }

    CP_WAIT0();
    __syncthreads();

    for (int cp = 0; cp < 40; ++cp) {
        const char* cur = smem + ((cp & 1) ? OFF_W1 : OFF_W0);
        if (cp + 1 < 40) {
            fill_W2_async(smem, (cp & 1) ? OFF_W0 : OFF_W1, WT, 2 * (cp + 1), tid);
            CP_COMMIT();
        }

#pragma unroll
        for (int sub = 0; sub < 2; ++sub) {
            const int ch = 2 * cp + sub;
            const uint32_t* wb = reinterpret_cast<const uint32_t*>(cur + sub * 16384);

            float c[4][4];
#pragma unroll
            for (int ntl = 0; ntl < 4; ++ntl) {
                const float2 bb = *reinterpret_cast<const float2*>(
                    sBias + ch * 64 + (nh * 4 + ntl) * 8 + la * 2);
                c[ntl][0] = bb.x; c[ntl][1] = bb.y;
                c[ntl][2] = bb.x; c[ntl][3] = bb.y;
            }

#pragma unroll
            for (int ks = 0; ks < 8; ++ks) {
#pragma unroll
                for (int ntl = 0; ntl < 4; ++ntl) {
                    const int nrow = (nh * 4 + ntl) * 8 + lq;
                    const int base = nrow * 64;
                    uint32_t b0 = wb[base + (((2 * ks)     ^ lq) * 4) + la];
                    uint32_t b1 = wb[base + (((2 * ks + 1) ^ lq) * 4) + la];
                    mma_f16_m16n8k16(c[ntl], A0[ks], A1[ks], A2[ks], A3[ks], b0, b1);
                }
            }

            if (PASS == 2 || ch < 64) {
                float s0 = sS[r0 * 81 + ch];
                float s1 = sS[r1 * 81 + ch];
#pragma unroll
                for (int ntl = 0; ntl < 4; ++ntl) {
                    accA[ntl][0] = fmaf(s0, c[ntl][0], accA[ntl][0]);
                    accA[ntl][1] = fmaf(s0, c[ntl][1], accA[ntl][1]);
                    accA[ntl][2] = fmaf(s1, c[ntl][2], accA[ntl][2]);
                    accA[ntl][3] = fmaf(s1, c[ntl][3], accA[ntl][3]);
                }
            } else if (ch < 72) {
#pragma unroll
                for (int ntl = 0; ntl < 4; ++ntl) {
                    int i = (ch - 64) * 8 + nh * 4 + ntl;
                    float s0 = sS[r0 * 81 + i];
                    float s1 = sS[r1 * 81 + i];
                    accB[0] = fmaf(s0, c[ntl][0], accB[0]);
                    accB[1] = fmaf(s0, c[ntl][1], accB[1]);
                    accB[2] = fmaf(s1, c[ntl][2], accB[2]);
                    accB[3] = fmaf(s1, c[ntl][3], accB[3]);
                }
            } else {
#pragma unroll
                for (int ntl = 0; ntl < 4; ++ntl) {
                    int i = (ch - 72) * 8 + nh * 4 + ntl;
                    float s0 = sS[r0 * 81 + i];
                    float s1 = sS[r1 * 81 + i];
                    accC[0] = fmaf(s0, c[ntl][0], accC[0]);
                    accC[1] = fmaf(s0, c[ntl][1], accC[1]);
                    accC[2] = fmaf(s1, c[ntl][2], accC[2]);
                    accC[3] = fmaf(s1, c[ntl][3], accC[3]);
                }
            }
        }

        if (cp + 1 < 40) CP_WAIT0();
        __syncthreads();
    }

    // ---- epilogue scatter ----
#pragma unroll
    for (int e = 0; e < 2; ++e) {
        int r = e ? r1 : r0;
        if (r >= ne) continue;
        int src = ei[e0 + r];
        if (PASS == 1) {
            const float C1 = 0.125f;
            float* d1 = g_h1 + (size_t)src * 128;
#pragma unroll
            for (int ntl = 0; ntl < 4; ++ntl) {
                int col = (nh * 4 + ntl) * 8 + la * 2;
                atomicAdd(d1 + col,     C1 * accA[ntl][e * 2]);
                atomicAdd(d1 + col + 1, C1 * accA[ntl][e * 2 + 1]);
            }
            float sh[8];
#pragma unroll
            for (int m = 0; m < 8; ++m) sh[m] = g_shb[(size_t)(e0 + r) * 8 + m];
#pragma unroll
            for (int b = 0; b < 2; ++b) {
                int k = la * 2 + b;
                float a1v = C1 * accB[e * 2 + b];
                float a2v = C1 * accC[e * 2 + b];
#pragma unroll
                for (int m = 0; m < 3; ++m)
                    atomicAdd(d1 + 64 + k * 3 + m, a1v * sh[m]);
#pragma unroll
                for (int m = 0; m < 5; ++m)
                    atomicAdd(d1 + 88 + k * 5 + m, a2v * sh[3 + m]);
            }
            if (nh == 0 && la == 0) atomicAdd(&g_cnt[src], 1.0f);
        } else {
            const float INV = 0.11180339887498948f;  // 1/sqrt(80)
            float* d2 = g_h2 + (size_t)src * 64;
#pragma unroll
            for (int ntl = 0; ntl < 4; ++ntl) {
                int col = (nh * 4 + ntl) * 8 + la * 2;
                atomicAdd(d2 + col,     INV * accA[ntl][e * 2]);
                atomicAdd(d2 + col + 1, INV * accA[ntl][e * 2 + 1]);
            }
        }
    }
}

// ---------------- fused h2 finalize + batch-norm stats ----------------------
__global__ void bn_stats_kernel(int Nn)
{
    __shared__ float rs[256], rs2[256];
    const int c = blockIdx.x;
    float s = 0.0f, s2 = 0.0f;
    for (int n = threadIdx.x; n < Nn; n += 256) {
        float x = g_h2[(size_t)n * 64 + c] / fmaxf(g_cnt[n], 1.0f);
        g_h2[(size_t)n * 64 + c] = x;
        s += x; s2 += x * x;
    }
    rs[threadIdx.x] = s; rs2[threadIdx.x] = s2;
    __syncthreads();
    for (int off = 128; off > 0; off >>= 1) {
        if (threadIdx.x < off) {
            rs[threadIdx.x]  += rs[threadIdx.x + off];
            rs2[threadIdx.x] += rs2[threadIdx.x + off];
        }
        __syncthreads();
    }
    if (threadIdx.x == 0) {
        float mu = rs[0] / (float)Nn;
        g_mu[c]  = mu;
        g_var[c] = rs2[0] / (float)Nn - mu * mu;
    }
}

__global__ void bn_apply_kernel(const float* __restrict__ gamma,
                                const float* __restrict__ beta, int Nn)
{
    int t = blockIdx.x * blockDim.x + threadIdx.x;
    int gs = gridDim.x * blockDim.x;
    for (int idx = t; idx < Nn * 64; idx += gs) {
        int c = idx & 63;
        float x = (g_h2[idx] - g_mu[c]) * rsqrtf(g_var[c] + 1e-5f) * gamma[c] + beta[c];
        g_sph[idx] = softplusf(x);
    }
}

// ---------------- launch ----------------------------------------------------
extern "C" void kernel_launch(void* const* d_in, const int* in_sizes, int n_in,
                              void* d_out, int out_size)
{
    const float* node_feature = (const float*)d_in[0];
    const int*   edge_index   = (const int*)d_in[1];
    const float* edge_feature = (const float*)d_in[2];
    const float* edge_vec     = (const float*)d_in[3];
    const float* w_node = (const float*)d_in[4];
    const float* b_node = (const float*)d_in[5];
    const float* w_skip = (const float*)d_in[6];
    const float* b_skip = (const float*)d_in[7];
    const float* fc1_w1 = (const float*)d_in[8];
    const float* fc1_b1 = (const float*)d_in[9];
    const float* fc1_w2 = (const float*)d_in[10];
    const float* fc1_b2 = (const float*)d_in[11];
    const float* fc2_w1 = (const float*)d_in[12];
    const float* fc2_b1 = (const float*)d_in[13];
    const float* fc2_w2 = (const float*)d_in[14];
    const float* fc2_b2 = (const float*)d_in[15];
    const float* bn_gamma = (const float*)d_in[16];
    const float* bn_beta  = (const float*)d_in[17];
    const float* w_out = (const float*)d_in[18];
    const float* b_out = (const float*)d_in[19];
    float* out = (float*)d_out;

    const int Nn = in_sizes[0] / 256;   // 10000
    const int E  = in_sizes[2] / 128;   // 40000

    float *p_skip, *p_h, *p_sph;
    __half *p_u1h, *p_u2h, *p_w1t, *p_w2t, *p_wt1a, *p_wt1b;
    cudaGetSymbolAddress((void**)&p_skip, g_skip);
    cudaGetSymbolAddress((void**)&p_h,    g_h);
    cudaGetSymbolAddress((void**)&p_u1h,  g_u1h);
    cudaGetSymbolAddress((void**)&p_u2h,  g_u2h);
    cudaGetSymbolAddress((void**)&p_sph,  g_sph);
    cudaGetSymbolAddress((void**)&p_w1t,  g_w1t);
    cudaGetSymbolAddress((void**)&p_w2t,  g_w2t);
    cudaGetSymbolAddress((void**)&p_wt1a, g_wt1a);
    cudaGetSymbolAddress((void**)&p_wt1b, g_wt1b);

    cudaFuncSetAttribute((const void*)msg_mma_kernel<1>,
                         cudaFuncAttributeMaxDynamicSharedMemorySize, SMEM_MSG_B);
    cudaFuncSetAttribute((const void*)msg_mma_kernel<2>,
                         cudaFuncAttributeMaxDynamicSharedMemorySize, SMEM_MSG_B);

    // weight transposes (fp16) + fused sh/zero prep
    transpose_kernel<<<dim3(160, 4), dim3(32, 8)>>>(fc1_w2, p_w1t);
    transpose_kernel<<<dim3(160, 4), dim3(32, 8)>>>(fc2_w2, p_w2t);
    transpose128_kernel<<<dim3(4, 4), dim3(32, 8)>>>(fc1_w1, p_wt1a);
    transpose128_kernel<<<dim3(4, 4), dim3(32, 8)>>>(fc2_w1, p_wt1b);
    prep_kernel<<<256, 256>>>(edge_vec, E, Nn);

    // node-side GEMMs (fp32 out, scalar)
    gemm_kernel<0, 0><<<dim3(4, (Nn + 63) / 64), 256>>>(
        node_feature, w_skip, b_skip, nullptr, p_skip, Nn, 256, 256);
    gemm_kernel<0, 0><<<dim3(1, (Nn + 63) / 64), 256>>>(
        node_feature, w_node, b_node, nullptr, p_h, Nn, 64, 256);

    // edge MLP first layers via fp16 MMA (softplus, fp16 out)
    const int ublk = (E + 127) / 128;
    ugemm_kernel<<<ublk, 512>>>(edge_feature, p_wt1a, fc1_b1, p_u1h, E);
    ugemm_kernel<<<ublk, 512>>>(edge_feature, p_wt1b, fc2_b1, p_u2h, E);

    const int nblk = (E + EBLK - 1) / EBLK;
    msg_mma_kernel<1><<<nblk, NTHR, SMEM_MSG_B>>>(edge_index, p_u1h, p_w1t, fc1_b2, E);
    msg_mma_kernel<2><<<nblk, NTHR, SMEM_MSG_B>>>(edge_index, p_u2h, p_w2t, fc2_b2, E);

    bn_stats_kernel<<<64, 256>>>(Nn);
    bn_apply_kernel<<<256, 256>>>(bn_gamma, bn_beta, Nn);

    // out = softplus(sph @ w_out + b_out) + skip
    gemm_kernel<1, 1><<<dim3(4, (Nn + 63) / 64), 256>>>(
        p_sph, w_out, b_out, p_skip, out, Nn, 256, 64);
}

// round 12
// speedup vs baseline: 1.5936x; 1.0558x over previous
#include <cuda_runtime.h>
#include <cuda_fp16.h>
#include <math.h>
#include <stdint.h>

// Problem constants: N=10000, E=40000, IN_CH=256, OUT_CH=256,
// EDGE_DIM=128, NS=64, NV=8, WN1=WN2=5120.

#define MAXN 10000
#define MAXE 40000

// ---------------- scratch (static __device__ — no allocations allowed) -----
__device__ float  g_skip[MAXN * 256];
__device__ float  g_h   [MAXN * 64];
__device__ __half g_u1h [MAXE * 128];
__device__ __half g_u2h [MAXE * 128];
__device__ float  g_shb [MAXE * 8];     // sh1 (3) + sh2 (5)
__device__ float  g_h1  [MAXN * 128];   // RAW msg1 sums (finalized inline in msg2)
__device__ float  g_cnt [MAXN];
__device__ float  g_h2  [MAXN * 64];
__device__ float  g_mu  [64];
__device__ float  g_var [64];
__device__ float  g_sph [MAXN * 64];
__device__ __half g_w1t [5120 * 128];   // fc1_w2 transposed [5120,128], fp16
__device__ __half g_w2t [5120 * 128];   // fc2_w2 transposed, fp16
__device__ __half g_wt1a[128 * 128];    // fc1_w1 transposed, fp16
__device__ __half g_wt1b[128 * 128];    // fc2_w1 transposed, fp16

__device__ __forceinline__ float softplusf(float x) {
    return fmaxf(x, 0.0f) + log1pf(expf(-fabsf(x)));
}
__device__ __forceinline__ uint32_t smem_u32(const void* p) {
    uint32_t a;
    asm("{ .reg .u64 t; cvta.to.shared.u64 t, %1; cvt.u32.u64 %0, t; }"
        : "=r"(a) : "l"(p));
    return a;
}
__device__ __forceinline__ uint32_t pack_h2(float x, float y) {
    __half2 h = __floats2half2_rn(x, y);
    return *reinterpret_cast<uint32_t*>(&h);
}
__device__ __forceinline__ void mma_f16_m16n8k16(float c[4],
    uint32_t a0, uint32_t a1, uint32_t a2, uint32_t a3,
    uint32_t b0, uint32_t b1)
{
    asm volatile(
        "mma.sync.aligned.m16n8k16.row.col.f32.f16.f16.f32 "
        "{%0,%1,%2,%3}, {%4,%5,%6,%7}, {%8,%9}, {%0,%1,%2,%3};"
        : "+f"(c[0]), "+f"(c[1]), "+f"(c[2]), "+f"(c[3])
        : "r"(a0), "r"(a1), "r"(a2), "r"(a3), "r"(b0), "r"(b1));
}
#define CP_ASYNC16(dst, src) \
    asm volatile("cp.async.cg.shared.global [%0], [%1], 16;" :: "r"(dst), "l"(src))
#define CP_COMMIT()  asm volatile("cp.async.commit_group;" ::: "memory")
#define CP_WAIT0()   asm volatile("cp.async.wait_group 0;" ::: "memory")

// ======================= generic fp32 GEMM (small mats) =====================
template <int ACT, int ADD>
__global__ void __launch_bounds__(256) gemm_kernel(
    const float* __restrict__ A, const float* __restrict__ B,
    const float* __restrict__ bias, const float* __restrict__ addsrc,
    float* __restrict__ C, int M, int N, int K)
{
    __shared__ float As[16][64];
    __shared__ float Bs[16][64];
    const int bm = blockIdx.y * 64, bn = blockIdx.x * 64;
    const int tid = threadIdx.x;
    const int ty = tid >> 4, tx = tid & 15;

    float acc[4][4] = {};
    for (int k0 = 0; k0 < K; k0 += 16) {
#pragma unroll
        for (int l = 0; l < 4; ++l) {
            int idx = tid + l * 256;
            int r = idx >> 4, c = idx & 15;
            int gr = bm + r;
            As[c][r] = (gr < M) ? A[(size_t)gr * K + k0 + c] : 0.0f;
        }
#pragma unroll
        for (int l = 0; l < 4; ++l) {
            int idx = tid + l * 256;
            int r = idx >> 6, c = idx & 63;
            Bs[r][c] = B[(size_t)(k0 + r) * N + bn + c];
        }
        __syncthreads();
#pragma unroll
        for (int kk = 0; kk < 16; ++kk) {
            float ra[4], rb[4];
#pragma unroll
            for (int a = 0; a < 4; ++a) ra[a] = As[kk][ty * 4 + a];
#pragma unroll
            for (int b = 0; b < 4; ++b) rb[b] = Bs[kk][tx * 4 + b];
#pragma unroll
            for (int a = 0; a < 4; ++a)
#pragma unroll
                for (int b = 0; b < 4; ++b)
                    acc[a][b] = fmaf(ra[a], rb[b], acc[a][b]);
        }
        __syncthreads();
    }
#pragma unroll
    for (int a = 0; a < 4; ++a) {
        int m = bm + ty * 4 + a;
        if (m >= M) continue;
#pragma unroll
        for (int b = 0; b < 4; ++b) {
            int n = bn + tx * 4 + b;
            float v = acc[a][b] + bias[n];
            if (ACT) v = softplusf(v);
            if (ADD) v += addsrc[(size_t)m * N + n];
            C[(size_t)m * N + n] = v;
        }
    }
}

// ---- weight transpose [128,5120] -> [5120,128], converted to fp16 ---------
__global__ void transpose_kernel(const float* __restrict__ W, __half* __restrict__ WT)
{
    __shared__ float t[32][33];
    const int j0 = blockIdx.x * 32, d0 = blockIdx.y * 32;
    for (int r = threadIdx.y; r < 32; r += 8)
        t[r][threadIdx.x] = W[(size_t)(d0 + r) * 5120 + j0 + threadIdx.x];
    __syncthreads();
    for (int r = threadIdx.y; r < 32; r += 8)
        WT[(size_t)(j0 + r) * 128 + d0 + threadIdx.x] =
            __float2half_rn(t[threadIdx.x][r]);
}

// ---- transpose [128,128] fp32 -> fp16 --------------------------------------
__global__ void transpose128_kernel(const float* __restrict__ W, __half* __restrict__ WT)
{
    __shared__ float t[32][33];
    const int n0 = blockIdx.x * 32, k0 = blockIdx.y * 32;
    for (int r = threadIdx.y; r < 32; r += 8)
        t[r][threadIdx.x] = W[(size_t)(k0 + r) * 128 + n0 + threadIdx.x];
    __syncthreads();
    for (int r = threadIdx.y; r < 32; r += 8)
        WT[(size_t)(n0 + r) * 128 + k0 + threadIdx.x] =
            __float2half_rn(t[threadIdx.x][r]);
}

// ---------------- fused prep: spherical harmonics + zeroing -----------------
__global__ void prep_kernel(const float* __restrict__ ev, int E, int Nn)
{
    int t = blockIdx.x * blockDim.x + threadIdx.x;
    int gs = gridDim.x * blockDim.x;
    for (int e = t; e < E; e += gs) {
        float x = ev[e * 3 + 0], y = ev[e * 3 + 1], z = ev[e * 3 + 2];
        float rn = rsqrtf(x * x + y * y + z * z);
        x *= rn; y *= rn; z *= rn;
        const float s3 = 1.7320508075688772f;
        const float s5 = 2.2360679774997896f;
        float* o = g_shb + (size_t)e * 8;
        o[0] = s3 * x;
        o[1] = s3 * y;
        o[2] = s3 * z;
        o[3] = s5 * s3 * x * z;
        o[4] = s5 * s3 * x * y;
        o[5] = s5 * (y * y - 0.5f * (x * x + z * z));
        o[6] = s5 * s3 * y * z;
        o[7] = s5 * (s3 * 0.5f) * (z * z - x * x);
    }
    for (int i = t; i < Nn * 128; i += gs) g_h1[i] = 0.0f;
    for (int i = t; i < Nn * 64;  i += gs) g_h2[i] = 0.0f;
    for (int i = t; i < Nn;       i += gs) g_cnt[i] = 0.0f;
}

// ======================= fp16 MMA first-layer GEMM ==========================
__global__ void __launch_bounds__(512) ugemm_kernel(
    const float* __restrict__ A, const __half* __restrict__ WT,
    const float* __restrict__ bias, __half* __restrict__ Out, int M)
{
    __shared__ __align__(16) char ws[32768];
    const int tid = threadIdx.x;
    const int wid = tid >> 5, lane = tid & 31;
    const int mt = wid >> 1, nh = wid & 1;
    const int lq = lane >> 2, la = lane & 3;

    for (int idx = tid; idx < 2048; idx += 512) {
        int row = idx >> 4, q = idx & 15;
        const __half* src = WT + (size_t)row * 128 + q * 8;
        uint32_t dst = smem_u32(ws + row * 256 + ((q ^ (row & 7)) * 16));
        CP_ASYNC16(dst, src);
    }
    CP_COMMIT();

    const int r0 = blockIdx.x * 128 + mt * 16 + lq;
    const int r1 = r0 + 8;
    const bool v0 = r0 < M, v1 = r1 < M;

    uint32_t A0[8], A1[8], A2[8], A3[8];
    {
        const float* a0p = A + (size_t)(v0 ? r0 : 0) * 128 + 2 * la;
        const float* a1p = A + (size_t)(v1 ? r1 : 0) * 128 + 2 * la;
#pragma unroll
        for (int ks = 0; ks < 8; ++ks) {
            float2 f0 = *reinterpret_cast<const float2*>(a0p + ks * 16);
            float2 f2 = *reinterpret_cast<const float2*>(a0p + ks * 16 + 8);
            float2 f1 = *reinterpret_cast<const float2*>(a1p + ks * 16);
            float2 f3 = *reinterpret_cast<const float2*>(a1p + ks * 16 + 8);
            A0[ks] = v0 ? pack_h2(f0.x, f0.y) : 0u;
            A2[ks] = v0 ? pack_h2(f2.x, f2.y) : 0u;
            A1[ks] = v1 ? pack_h2(f1.x, f1.y) : 0u;
            A3[ks] = v1 ? pack_h2(f3.x, f3.y) : 0u;
        }
    }

    float c[8][4];
#pragma unroll
    for (int nt = 0; nt < 8; ++nt) {
        float2 bb = __ldg(reinterpret_cast<const float2*>(
            bias + (nh * 8 + nt) * 8 + la * 2));
        c[nt][0] = bb.x; c[nt][1] = bb.y;
        c[nt][2] = bb.x; c[nt][3] = bb.y;
    }

    CP_WAIT0();
    __syncthreads();
    const uint32_t* wb = reinterpret_cast<const uint32_t*>(ws);
#pragma unroll
    for (int ks = 0; ks < 8; ++ks) {
#pragma unroll
        for (int nt = 0; nt < 8; ++nt) {
            const int nrow = (nh * 8 + nt) * 8 + lq;
            const int base = nrow * 64;
            uint32_t b0 = wb[base + (((2 * ks)     ^ lq) * 4) + la];
            uint32_t b1 = wb[base + (((2 * ks + 1) ^ lq) * 4) + la];
            mma_f16_m16n8k16(c[nt], A0[ks], A1[ks], A2[ks], A3[ks], b0, b1);
        }
    }

#pragma unroll
    for (int nt = 0; nt < 8; ++nt) {
        int col = (nh * 8 + nt) * 8 + la * 2;
        if (v0) {
            __half2 h = __floats2half2_rn(softplusf(c[nt][0]), softplusf(c[nt][1]));
            *reinterpret_cast<__half2*>(Out + (size_t)r0 * 128 + col) = h;
        }
        if (v1) {
            __half2 h = __floats2half2_rn(softplusf(c[nt][2]), softplusf(c[nt][3]));
            *reinterpret_cast<__half2*>(Out + (size_t)r1 * 128 + col) = h;
        }
    }
}

// ======================= fp16 mma.sync fused message pass ====================
// 96 edges/CTA, 384 threads, 12 warps, 1 CTA/SM. 20 chunk-QUADS: each round
// cp.async-fills 4 W chunks (64KB) double-buffered; one sync per quad.
// B-fragment LDS software-pipelined one ks-step ahead of the MMAs.
// PASS2 finalizes h1 inline while building S.
//
// smem bytes: sW0 @0 (65536 = 4 chunks), sW1 @65536 (65536),
//             sS @131072 (96x81 fp32 = 31104), sBias @162176 (20480).
#define EBLK     96
#define NTHR     384
#define OFF_W0   0
#define OFF_W1   65536
#define OFF_SS   131072
#define OFF_BIAS 162176
#define SMEM_MSG_B 182656

__device__ __forceinline__ void fill_W4_async(char* smem, uint32_t bufoff,
    const __half* __restrict__ WT, int ch0, int tid)
{
    for (int idx = tid; idx < 4096; idx += NTHR) {
        int sub = idx >> 10;              // 0..3
        int w   = idx & 1023;
        int row = w >> 4;
        int q   = w & 15;
        const __half* src = WT + ((size_t)(ch0 + sub) * 64 + row) * 128 + q * 8;
        uint32_t dst = smem_u32(smem + bufoff + sub * 16384 +
                                row * 256 + ((q ^ (row & 7)) * 16));
        CP_ASYNC16(dst, src);
    }
}

template <int PASS>
__global__ void __launch_bounds__(NTHR, 1) msg_mma_kernel(
    const int* __restrict__ ei, const __half* __restrict__ Uh,
    const __half* __restrict__ WT, const float* __restrict__ B2, int E)
{
    extern __shared__ __align__(16) char smem[];
    float* sS    = reinterpret_cast<float*>(smem + OFF_SS);     // [96][81]
    float* sBias = reinterpret_cast<float*>(smem + OFF_BIAS);   // [5120]

    const int tid = threadIdx.x;
    const int wid = tid >> 5, lane = tid & 31;
    const int mt = wid >> 1, nh = wid & 1;
    const int lq = lane >> 2, la = lane & 3;
    const int e0 = blockIdx.x * EBLK;
    const int ne = min(EBLK, E - e0);
    const int r0 = mt * 16 + lq, r1 = r0 + 8;
    const bool v0 = r0 < ne, v1 = r1 < ne;

    fill_W4_async(smem, OFF_W0, WT, 0, tid);
    CP_COMMIT();

    // bias to smem
    for (int i = tid; i < 5120; i += NTHR) sBias[i] = B2[i];

    // ---- S tile ----
    if (PASS == 1) {
        for (int idx = tid; idx < EBLK * 64; idx += NTHR) {
            int e = idx >> 6, i = idx & 63;
            float v = 0.0f;
            if (e < ne) {
                int dst = ei[E + e0 + e];
                v = g_h[(size_t)dst * 64 + i];
            }
            sS[e * 81 + i] = v;
        }
    } else {
        for (int idx = tid; idx < EBLK * 80; idx += NTHR) {
            int e = idx / 80, j = idx - e * 80;
            float v = 0.0f;
            if (e < ne) {
                int dst = ei[E + e0 + e];
                float rc = 1.0f / fmaxf(g_cnt[dst], 1.0f);
                const float* he = g_h1 + (size_t)dst * 128;
                if (j < 64) {
                    v = he[j] * rc + g_h[(size_t)dst * 64 + j];
                } else if (j < 72) {
                    int i = j - 64; float p = 0.0f;
#pragma unroll
                    for (int m = 0; m < 3; ++m)
                        p += he[64 + i * 3 + m] * g_shb[(size_t)(e0 + e) * 8 + m];
                    v = p * rc * 0.5773502691896258f;
                } else {
                    int i = j - 72; float p = 0.0f;
#pragma unroll
                    for (int m = 0; m < 5; ++m)
                        p += he[88 + i * 5 + m] * g_shb[(size_t)(e0 + e) * 8 + 3 + m];
                    v = p * rc * 0.4472135954999579f;
                }
            }
            sS[e * 81 + j] = v;
        }
    }

    // ---- A registers: U rows r0, r1 as half2 ----
    uint32_t A0[8], A1[8], A2[8], A3[8];
    {
        const uint32_t* u0 = reinterpret_cast<const uint32_t*>(
            Uh + (size_t)(e0 + (v0 ? r0 : 0)) * 128) + la;
        const uint32_t* u1 = reinterpret_cast<const uint32_t*>(
            Uh + (size_t)(e0 + (v1 ? r1 : 0)) * 128) + la;
#pragma unroll
        for (int ks = 0; ks < 8; ++ks) {
            A0[ks] = v0 ? u0[ks * 8]     : 0u;
            A2[ks] = v0 ? u0[ks * 8 + 4] : 0u;
            A1[ks] = v1 ? u1[ks * 8]     : 0u;
            A3[ks] = v1 ? u1[ks * 8 + 4] : 0u;
        }
    }

    float accA[4][4];
    float accB[4], accC[4];
#pragma unroll
    for (int i = 0; i < 4; ++i) {
#pragma unroll
        for (int j = 0; j < 4; ++j) accA[i][j] = 0.0f;
        accB[i] = 0.0f; accC[i] = 0.0f;
    }

    // per-thread B-fragment offsets (within a chunk buffer, in words)
    int boff[4][2];   // [ntl][b01]
#pragma unroll
    for (int ntl = 0; ntl < 4; ++ntl) {
        const int nrow = (nh * 4 + ntl) * 8 + lq;
#pragma unroll
        for (int b = 0; b < 2; ++b)
            boff[ntl][b] = nrow * 64 + 0 /*ks*/ + ((b ^ lq) * 4) + la;
        // note: full index = nrow*64 + (((2ks+b)^lq)*4)+la, computed in loop
    }

    CP_WAIT0();
    __syncthreads();

    for (int qd = 0; qd < 20; ++qd) {
        const char* cur = smem + ((qd & 1) ? OFF_W1 : OFF_W0);
        if (qd + 1 < 20) {
            fill_W4_async(smem, (qd & 1) ? OFF_W0 : OFF_W1, WT, 4 * (qd + 1), tid);
            CP_COMMIT();
        }

#pragma unroll
        for (int sub = 0; sub < 4; ++sub) {
            const int ch = 4 * qd + sub;
            const uint32_t* wb = reinterpret_cast<const uint32_t*>(cur + sub * 16384);

            float c[4][4];
#pragma unroll
            for (int ntl = 0; ntl < 4; ++ntl) {
                const float2 bb = *reinterpret_cast<const float2*>(
                    sBias + ch * 64 + (nh * 4 + ntl) * 8 + la * 2);
                c[ntl][0] = bb.x; c[ntl][1] = bb.y;
                c[ntl][2] = bb.x; c[ntl][3] = bb.y;
            }

            // software-pipelined B loads: fetch ks+1 while MMA-ing ks
            uint32_t bcur[4][2], bnxt[4][2];
#pragma unroll
            for (int ntl = 0; ntl < 4; ++ntl) {
                const int base = ((nh * 4 + ntl) * 8 + lq) * 64;
                bcur[ntl][0] = wb[base + (((0) ^ lq) * 4) + la];
                bcur[ntl][1] = wb[base + (((1) ^ lq) * 4) + la];
            }
#pragma unroll
            for (int ks = 0; ks < 8; ++ks) {
                if (ks < 7) {
#pragma unroll
                    for (int ntl = 0; ntl < 4; ++ntl) {
                        const int base = ((nh * 4 + ntl) * 8 + lq) * 64;
                        bnxt[ntl][0] = wb[base + (((2 * ks + 2) ^ lq) * 4) + la];
                        bnxt[ntl][1] = wb[base + (((2 * ks + 3) ^ lq) * 4) + la];
                    }
                }
#pragma unroll
                for (int ntl = 0; ntl < 4; ++ntl)
                    mma_f16_m16n8k16(c[ntl], A0[ks], A1[ks], A2[ks], A3[ks],
                                     bcur[ntl][0], bcur[ntl][1]);
#pragma unroll
                for (int ntl = 0; ntl < 4; ++ntl) {
                    bcur[ntl][0] = bnxt[ntl][0];
                    bcur[ntl][1] = bnxt[ntl][1];
                }
            }

            if (PASS == 2 || ch < 64) {
                float s0 = sS[r0 * 81 + ch];
                float s1 = sS[r1 * 81 + ch];
#pragma unroll
                for (int ntl = 0; ntl < 4; ++ntl) {
                    accA[ntl][0] = fmaf(s0, c[ntl][0], accA[ntl][0]);
                    accA[ntl][1] = fmaf(s0, c[ntl][1], accA[ntl][1]);
                    accA[ntl][2] = fmaf(s1, c[ntl][2], accA[ntl][2]);
                    accA[ntl][3] = fmaf(s1, c[ntl][3], accA[ntl][3]);
                }
            } else if (ch < 72) {
#pragma unroll
                for (int ntl = 0; ntl < 4; ++ntl) {
                    int i = (ch - 64) * 8 + nh * 4 + ntl;
                    float s0 = sS[r0 * 81 + i];
                    float s1 = sS[r1 * 81 + i];
                    accB[0] = fmaf(s0, c[ntl][0], accB[0]);
                    accB[1] = fmaf(s0, c[ntl][1], accB[1]);
                    accB[2] = fmaf(s1, c[ntl][2], accB[2]);
                    accB[3] = fmaf(s1, c[ntl][3], accB[3]);
                }
            } else {
#pragma unroll
                for (int ntl = 0; ntl < 4; ++ntl) {
                    int i = (ch - 72) * 8 + nh * 4 + ntl;
                    float s0 = sS[r0 * 81 + i];
                    float s1 = sS[r1 * 81 + i];
                    accC[0] = fmaf(s0, c[ntl][0], accC[0]);
                    accC[1] = fmaf(s0, c[ntl][1], accC[1]);
                    accC[2] = fmaf(s1, c[ntl][2], accC[2]);
                    accC[3] = fmaf(s1, c[ntl][3], accC[3]);
                }
            }
        }

        if (qd + 1 < 20) CP_WAIT0();
        __syncthreads();
    }

    // ---- epilogue scatter ----
#pragma unroll
    for (int e = 0; e < 2; ++e) {
        int r = e ? r1 : r0;
        if (r >= ne) continue;
        int src = ei[e0 + r];
        if (PASS == 1) {
            const float C1 = 0.125f;
            float* d1 = g_h1 + (size_t)src * 128;
#pragma unroll
            for (int ntl = 0; ntl < 4; ++ntl) {
                int col = (nh * 4 + ntl) * 8 + la * 2;
                atomicAdd(d1 + col,     C1 * accA[ntl][e * 2]);
                atomicAdd(d1 + col + 1, C1 * accA[ntl][e * 2 + 1]);
            }
            float sh[8];
#pragma unroll
            for (int m = 0; m < 8; ++m) sh[m] = g_shb[(size_t)(e0 + r) * 8 + m];
#pragma unroll
            for (int b = 0; b < 2; ++b) {
                int k = la * 2 + b;
                float a1v = C1 * accB[e * 2 + b];
                float a2v = C1 * accC[e * 2 + b];
#pragma unroll
                for (int m = 0; m < 3; ++m)
                    atomicAdd(d1 + 64 + k * 3 + m, a1v * sh[m]);
#pragma unroll
                for (int m = 0; m < 5; ++m)
                    atomicAdd(d1 + 88 + k * 5 + m, a2v * sh[3 + m]);
            }
            if (nh == 0 && la == 0) atomicAdd(&g_cnt[src], 1.0f);
        } else {
            const float INV = 0.11180339887498948f;  // 1/sqrt(80)
            float* d2 = g_h2 + (size_t)src * 64;
#pragma unroll
            for (int ntl = 0; ntl < 4; ++ntl) {
                int col = (nh * 4 + ntl) * 8 + la * 2;
                atomicAdd(d2 + col,     INV * accA[ntl][e * 2]);
                atomicAdd(d2 + col + 1, INV * accA[ntl][e * 2 + 1]);
            }
        }
    }
}

// ---------------- fused h2 finalize + batch-norm stats ----------------------
__global__ void bn_stats_kernel(int Nn)
{
    __shared__ float rs[256], rs2[256];
    const int c = blockIdx.x;
    float s = 0.0f, s2 = 0.0f;
    for (int n = threadIdx.x; n < Nn; n += 256) {
        float x = g_h2[(size_t)n * 64 + c] / fmaxf(g_cnt[n], 1.0f);
        g_h2[(size_t)n * 64 + c] = x;
        s += x; s2 += x * x;
    }
    rs[threadIdx.x] = s; rs2[threadIdx.x] = s2;
    __syncthreads();
    for (int off = 128; off > 0; off >>= 1) {
        if (threadIdx.x < off) {
            rs[threadIdx.x]  += rs[threadIdx.x + off];
            rs2[threadIdx.x] += rs2[threadIdx.x + off];
        }
        __syncthreads();
    }
    if (threadIdx.x == 0) {
        float mu = rs[0] / (float)Nn;
        g_mu[c]  = mu;
        g_var[c] = rs2[0] / (float)Nn - mu * mu;
    }
}

__global__ void bn_apply_kernel(const float* __restrict__ gamma,
                                const float* __restrict__ beta, int Nn)
{
    int t = blockIdx.x * blockDim.x + threadIdx.x;
    int gs = gridDim.x * blockDim.x;
    for (int idx = t; idx < Nn * 64; idx += gs) {
        int c = idx & 63;
        float x = (g_h2[idx] - g_mu[c]) * rsqrtf(g_var[c] + 1e-5f) * gamma[c] + beta[c];
        g_sph[idx] = softplusf(x);
    }
}

// ---------------- launch ----------------------------------------------------
extern "C" void kernel_launch(void* const* d_in, const int* in_sizes, int n_in,
                              void* d_out, int out_size)
{
    const float* node_feature = (const float*)d_in[0];
    const int*   edge_index   = (const int*)d_in[1];
    const float* edge_feature = (const float*)d_in[2];
    const float* edge_vec     = (const float*)d_in[3];
    const float* w_node = (const float*)d_in[4];
    const float* b_node = (const float*)d_in[5];
    const float* w_skip = (const float*)d_in[6];
    const float* b_skip = (const float*)d_in[7];
    const float* fc1_w1 = (const float*)d_in[8];
    const float* fc1_b1 = (const float*)d_in[9];
    const float* fc1_w2 = (const float*)d_in[10];
    const float* fc1_b2 = (const float*)d_in[11];
    const float* fc2_w1 = (const float*)d_in[12];
    const float* fc2_b1 = (const float*)d_in[13];
    const float* fc2_w2 = (const float*)d_in[14];
    const float* fc2_b2 = (const float*)d_in[15];
    const float* bn_gamma = (const float*)d_in[16];
    const float* bn_beta  = (const float*)d_in[17];
    const float* w_out = (const float*)d_in[18];
    const float* b_out = (const float*)d_in[19];
    float* out = (float*)d_out;

    const int Nn = in_sizes[0] / 256;   // 10000
    const int E  = in_sizes[2] / 128;   // 40000

    float *p_skip, *p_h, *p_sph;
    __half *p_u1h, *p_u2h, *p_w1t, *p_w2t, *p_wt1a, *p_wt1b;
    cudaGetSymbolAddress((void**)&p_skip, g_skip);
    cudaGetSymbolAddress((void**)&p_h,    g_h);
    cudaGetSymbolAddress((void**)&p_u1h,  g_u1h);
    cudaGetSymbolAddress((void**)&p_u2h,  g_u2h);
    cudaGetSymbolAddress((void**)&p_sph,  g_sph);
    cudaGetSymbolAddress((void**)&p_w1t,  g_w1t);
    cudaGetSymbolAddress((void**)&p_w2t,  g_w2t);
    cudaGetSymbolAddress((void**)&p_wt1a, g_wt1a);
    cudaGetSymbolAddress((void**)&p_wt1b, g_wt1b);

    cudaFuncSetAttribute((const void*)msg_mma_kernel<1>,
                         cudaFuncAttributeMaxDynamicSharedMemorySize, SMEM_MSG_B);
    cudaFuncSetAttribute((const void*)msg_mma_kernel<2>,
                         cudaFuncAttributeMaxDynamicSharedMemorySize, SMEM_MSG_B);

    // weight transposes (fp16) + fused sh/zero prep
    transpose_kernel<<<dim3(160, 4), dim3(32, 8)>>>(fc1_w2, p_w1t);
    transpose_kernel<<<dim3(160, 4), dim3(32, 8)>>>(fc2_w2, p_w2t);
    transpose128_kernel<<<dim3(4, 4), dim3(32, 8)>>>(fc1_w1, p_wt1a);
    transpose128_kernel<<<dim3(4, 4), dim3(32, 8)>>>(fc2_w1, p_wt1b);
    prep_kernel<<<256, 256>>>(edge_vec, E, Nn);

    // node-side GEMMs (fp32 out, scalar)
    gemm_kernel<0, 0><<<dim3(4, (Nn + 63) / 64), 256>>>(
        node_feature, w_skip, b_skip, nullptr, p_skip, Nn, 256, 256);
    gemm_kernel<0, 0><<<dim3(1, (Nn + 63) / 64), 256>>>(
        node_feature, w_node, b_node, nullptr, p_h, Nn, 64, 256);

    // edge MLP first layers via fp16 MMA (softplus, fp16 out)
    const int ublk = (E + 127) / 128;
    ugemm_kernel<<<ublk, 512>>>(edge_feature, p_wt1a, fc1_b1, p_u1h, E);
    ugemm_kernel<<<ublk, 512>>>(edge_feature, p_wt1b, fc2_b1, p_u2h, E);

    const int nblk = (E + EBLK - 1) / EBLK;
    msg_mma_kernel<1><<<nblk, NTHR, SMEM_MSG_B>>>(edge_index, p_u1h, p_w1t, fc1_b2, E);
    msg_mma_kernel<2><<<nblk, NTHR, SMEM_MSG_B>>>(edge_index, p_u2h, p_w2t, fc2_b2, E);

    bn_stats_kernel<<<64, 256>>>(Nn);
    bn_apply_kernel<<<256, 256>>>(bn_gamma, bn_beta, Nn);

    // out = softplus(sph @ w_out + b_out) + skip
    gemm_kernel<1, 1><<<dim3(4, (Nn + 63) / 64), 256>>>(
        p_sph, w_out, b_out, p_skip, out, Nn, 256, 64);
}

// round 13
// speedup vs baseline: 1.8352x; 1.1516x over previous
#include <cuda_runtime.h>
#include <cuda_fp16.h>
#include <math.h>
#include <stdint.h>

// Problem constants: N=10000, E=40000, IN_CH=256, OUT_CH=256,
// EDGE_DIM=128, NS=64, NV=8, WN1=WN2=5120.

#define MAXN 10000
#define MAXE 40000

// ---------------- scratch (static __device__ — no allocations allowed) -----
__device__ float  g_skip[MAXN * 256];
__device__ float  g_h   [MAXN * 64];
__device__ __half g_u1h [MAXE * 128];
__device__ __half g_u2h [MAXE * 128];
__device__ float  g_shb [MAXE * 8];     // sh1 (3) + sh2 (5)
__device__ float  g_h1  [MAXN * 128];   // RAW msg1 sums (finalized inline in msg2)
__device__ float  g_cnt [MAXN];
__device__ float  g_h2  [MAXN * 64];
__device__ float  g_mu  [64];
__device__ float  g_var [64];
__device__ __half g_sphh[MAXN * 64];    // softplus(bn) as fp16 for out-GEMM
__device__ __half g_w1t [5120 * 128];   // fc1_w2^T fp16
__device__ __half g_w2t [5120 * 128];   // fc2_w2^T fp16
__device__ __half g_wt1a[128 * 128];    // fc1_w1^T fp16
__device__ __half g_wt1b[128 * 128];    // fc2_w1^T fp16
__device__ __half g_wskt[256 * 256];    // w_skip^T fp16
__device__ __half g_wndt[64 * 256];     // w_node^T fp16
__device__ __half g_wott[256 * 64];     // w_out^T  fp16

__device__ __forceinline__ float softplusf(float x) {
    return fmaxf(x, 0.0f) + log1pf(expf(-fabsf(x)));
}
__device__ __forceinline__ uint32_t smem_u32(const void* p) {
    uint32_t a;
    asm("{ .reg .u64 t; cvta.to.shared.u64 t, %1; cvt.u32.u64 %0, t; }"
        : "=r"(a) : "l"(p));
    return a;
}
__device__ __forceinline__ uint32_t pack_h2(float x, float y) {
    __half2 h = __floats2half2_rn(x, y);
    return *reinterpret_cast<uint32_t*>(&h);
}
__device__ __forceinline__ void mma_f16_m16n8k16(float c[4],
    uint32_t a0, uint32_t a1, uint32_t a2, uint32_t a3,
    uint32_t b0, uint32_t b1)
{
    asm volatile(
        "mma.sync.aligned.m16n8k16.row.col.f32.f16.f16.f32 "
        "{%0,%1,%2,%3}, {%4,%5,%6,%7}, {%8,%9}, {%0,%1,%2,%3};"
        : "+f"(c[0]), "+f"(c[1]), "+f"(c[2]), "+f"(c[3])
        : "r"(a0), "r"(a1), "r"(a2), "r"(a3), "r"(b0), "r"(b1));
}
#define CP_ASYNC16(dst, src) \
    asm volatile("cp.async.cg.shared.global [%0], [%1], 16;" :: "r"(dst), "l"(src))
#define CP_COMMIT()  asm volatile("cp.async.commit_group;" ::: "memory")
#define CP_WAIT0()   asm volatile("cp.async.wait_group 0;" ::: "memory")

// ======================= mega-prep: all transposes + sh + zero ==============
// One launch. Blocks dispatched by range:
//   [0,640)    fc1_w2 [128,5120] -> g_w1t
//   [640,1280) fc2_w2            -> g_w2t
//   [1280,1296) fc1_w1 [128,128] -> g_wt1a
//   [1296,1312) fc2_w1           -> g_wt1b
//   [1312,1376) w_skip [256,256] -> g_wskt
//   [1376,1392) w_node [256,64]  -> g_wndt
//   [1392,1408) w_out  [64,256]  -> g_wott
//   [1408,1536) sh + zero (grid-stride, 128 blocks)
__device__ __forceinline__ void ttile(float (*t)[33],
    const float* __restrict__ W, __half* __restrict__ WT,
    int K, int N, int bx, int by, int tx, int ty)
{
    const int n0 = bx * 32, k0 = by * 32;
    for (int r = ty; r < 32; r += 8)
        t[r][tx] = W[(size_t)(k0 + r) * N + n0 + tx];
    __syncthreads();
    for (int r = ty; r < 32; r += 8)
        WT[(size_t)(n0 + r) * K + k0 + tx] = __float2half_rn(t[tx][r]);
}

__global__ void __launch_bounds__(256) megaprep_kernel(
    const float* __restrict__ ev, int E, int Nn,
    const float* __restrict__ fc1w2, const float* __restrict__ fc2w2,
    const float* __restrict__ fc1w1, const float* __restrict__ fc2w1,
    const float* __restrict__ wskip, const float* __restrict__ wnode,
    const float* __restrict__ wout)
{
    __shared__ float t[32][33];
    const int tx = threadIdx.x & 31, ty = threadIdx.x >> 5;
    int b = blockIdx.x;
    if (b < 640)  { ttile(t, fc1w2, g_w1t, 128, 5120, b % 160, b / 160, tx, ty); return; }
    b -= 640;
    if (b < 640)  { ttile(t, fc2w2, g_w2t, 128, 5120, b % 160, b / 160, tx, ty); return; }
    b -= 640;
    if (b < 16)   { ttile(t, fc1w1, g_wt1a, 128, 128, b % 4, b / 4, tx, ty); return; }
    b -= 16;
    if (b < 16)   { ttile(t, fc2w1, g_wt1b, 128, 128, b % 4, b / 4, tx, ty); return; }
    b -= 16;
    if (b < 64)   { ttile(t, wskip, g_wskt, 256, 256, b % 8, b / 8, tx, ty); return; }
    b -= 64;
    if (b < 16)   { ttile(t, wnode, g_wndt, 256, 64, b % 2, b / 2, tx, ty); return; }
    b -= 16;
    if (b < 16)   { ttile(t, wout, g_wott, 64, 256, b % 8, b / 8, tx, ty); return; }
    b -= 16;
    // sh + zero
    const int tid = b * 256 + threadIdx.x;
    const int gs = 128 * 256;
    for (int e = tid; e < E; e += gs) {
        float x = ev[e * 3 + 0], y = ev[e * 3 + 1], z = ev[e * 3 + 2];
        float rn = rsqrtf(x * x + y * y + z * z);
        x *= rn; y *= rn; z *= rn;
        const float s3 = 1.7320508075688772f;
        const float s5 = 2.2360679774997896f;
        float* o = g_shb + (size_t)e * 8;
        o[0] = s3 * x;
        o[1] = s3 * y;
        o[2] = s3 * z;
        o[3] = s5 * s3 * x * z;
        o[4] = s5 * s3 * x * y;
        o[5] = s5 * (y * y - 0.5f * (x * x + z * z));
        o[6] = s5 * s3 * y * z;
        o[7] = s5 * (s3 * 0.5f) * (z * z - x * x);
    }
    for (int i = tid; i < Nn * 128; i += gs) g_h1[i] = 0.0f;
    for (int i = tid; i < Nn * 64;  i += gs) g_h2[i] = 0.0f;
    for (int i = tid; i < Nn;       i += gs) g_cnt[i] = 0.0f;
}

// ======================= unified fp16 MMA GEMM ===============================
// Out[M, Ntot] = epi(A[M, K=KS*16] @ WT^T + bias [+ addsrc]).
// 512 thr, 16 warps: mt = wid>>1 (128 rows/CTA), nh = wid&1; warp covers NT
// n-tiles of 8 -> CTA N = NT*16. grid = (ceil(M/128), Ntot/(NT*16)).
// W rows staged via cp.async into XOR-swizzled dynamic smem.
template <int KS, int NT, int AHALF, int ACT, int ADD, int OUTH>
__global__ void __launch_bounds__(512) mma_gemm(
    const void* __restrict__ Av, const __half* __restrict__ WT,
    const float* __restrict__ bias, const float* __restrict__ addsrc,
    void* __restrict__ Outv, int M, int Ntot)
{
    constexpr int K = KS * 16;
    constexpr int CTAN = NT * 16;
    constexpr int ROWW = KS * 8;      // uint32 words per W smem row
    extern __shared__ __align__(16) char ws[];
    const int tid = threadIdx.x;
    const int wid = tid >> 5, lane = tid & 31;
    const int mt = wid >> 1, nh = wid & 1;
    const int lq = lane >> 2, la = lane & 3;
    const int bn0 = blockIdx.y * CTAN;

    for (int idx = tid; idx < CTAN * KS * 2; idx += 512) {
        int row = idx / (KS * 2);
        int q   = idx - row * (KS * 2);
        const __half* src = WT + (size_t)(bn0 + row) * K + q * 8;
        uint32_t dst = smem_u32(ws + row * (KS * 32) + ((q ^ (row & 7)) * 16));
        CP_ASYNC16(dst, src);
    }
    CP_COMMIT();

    const int r0 = blockIdx.x * 128 + mt * 16 + lq;
    const int r1 = r0 + 8;
    const bool v0 = r0 < M, v1 = r1 < M;

    uint32_t A0[KS], A1[KS], A2[KS], A3[KS];
    if (AHALF) {
        const uint32_t* u0 = reinterpret_cast<const uint32_t*>(
            (const __half*)Av + (size_t)(v0 ? r0 : 0) * K) + la;
        const uint32_t* u1 = reinterpret_cast<const uint32_t*>(
            (const __half*)Av + (size_t)(v1 ? r1 : 0) * K) + la;
#pragma unroll
        for (int ks = 0; ks < KS; ++ks) {
            A0[ks] = v0 ? u0[ks * 8]     : 0u;
            A2[ks] = v0 ? u0[ks * 8 + 4] : 0u;
            A1[ks] = v1 ? u1[ks * 8]     : 0u;
            A3[ks] = v1 ? u1[ks * 8 + 4] : 0u;
        }
    } else {
        const float* a0p = (const float*)Av + (size_t)(v0 ? r0 : 0) * K + 2 * la;
        const float* a1p = (const float*)Av + (size_t)(v1 ? r1 : 0) * K + 2 * la;
#pragma unroll
        for (int ks = 0; ks < KS; ++ks) {
            float2 f0 = *reinterpret_cast<const float2*>(a0p + ks * 16);
            float2 f2 = *reinterpret_cast<const float2*>(a0p + ks * 16 + 8);
            float2 f1 = *reinterpret_cast<const float2*>(a1p + ks * 16);
            float2 f3 = *reinterpret_cast<const float2*>(a1p + ks * 16 + 8);
            A0[ks] = v0 ? pack_h2(f0.x, f0.y) : 0u;
            A2[ks] = v0 ? pack_h2(f2.x, f2.y) : 0u;
            A1[ks] = v1 ? pack_h2(f1.x, f1.y) : 0u;
            A3[ks] = v1 ? pack_h2(f3.x, f3.y) : 0u;
        }
    }

    float c[NT][4];
#pragma unroll
    for (int nt = 0; nt < NT; ++nt) {
        float2 bb = __ldg(reinterpret_cast<const float2*>(
            bias + bn0 + (nh * NT + nt) * 8 + la * 2));
        c[nt][0] = bb.x; c[nt][1] = bb.y;
        c[nt][2] = bb.x; c[nt][3] = bb.y;
    }

    CP_WAIT0();
    __syncthreads();
    const uint32_t* wb = reinterpret_cast<const uint32_t*>(ws);
#pragma unroll
    for (int ks = 0; ks < KS; ++ks) {
#pragma unroll
        for (int nt = 0; nt < NT; ++nt) {
            const int base = ((nh * NT + nt) * 8 + lq) * ROWW;
            uint32_t b0 = wb[base + (((2 * ks)     ^ lq) * 4) + la];
            uint32_t b1 = wb[base + (((2 * ks + 1) ^ lq) * 4) + la];
            mma_f16_m16n8k16(c[nt], A0[ks], A1[ks], A2[ks], A3[ks], b0, b1);
        }
    }

#pragma unroll
    for (int nt = 0; nt < NT; ++nt) {
        const int gcol = bn0 + (nh * NT + nt) * 8 + la * 2;
#pragma unroll
        for (int e = 0; e < 2; ++e) {
            int r = e ? r1 : r0;
            if (e ? !v1 : !v0) continue;
            float x0 = c[nt][e * 2], x1 = c[nt][e * 2 + 1];
            if (ACT) { x0 = softplusf(x0); x1 = softplusf(x1); }
            if (ADD) {
                float2 ad = *reinterpret_cast<const float2*>(
                    addsrc + (size_t)r * Ntot + gcol);
                x0 += ad.x; x1 += ad.y;
            }
            if (OUTH) {
                *reinterpret_cast<__half2*>((__half*)Outv + (size_t)r * Ntot + gcol) =
                    __floats2half2_rn(x0, x1);
            } else {
                *reinterpret_cast<float2*>((float*)Outv + (size_t)r * Ntot + gcol) =
                    make_float2(x0, x1);
            }
        }
    }
}

// ======================= fp16 mma.sync fused message pass ====================
// (unchanged from R12 — proven 644us config)
#define EBLK     96
#define NTHR     384
#define OFF_W0   0
#define OFF_W1   65536
#define OFF_SS   131072
#define OFF_BIAS 162176
#define SMEM_MSG_B 182656

__device__ __forceinline__ void fill_W4_async(char* smem, uint32_t bufoff,
    const __half* __restrict__ WT, int ch0, int tid)
{
    for (int idx = tid; idx < 4096; idx += NTHR) {
        int sub = idx >> 10;
        int w   = idx & 1023;
        int row = w >> 4;
        int q   = w & 15;
        const __half* src = WT + ((size_t)(ch0 + sub) * 64 + row) * 128 + q * 8;
        uint32_t dst = smem_u32(smem + bufoff + sub * 16384 +
                                row * 256 + ((q ^ (row & 7)) * 16));
        CP_ASYNC16(dst, src);
    }
}

template <int PASS>
__global__ void __launch_bounds__(NTHR, 1) msg_mma_kernel(
    const int* __restrict__ ei, const __half* __restrict__ Uh,
    const __half* __restrict__ WT, const float* __restrict__ B2, int E)
{
    extern __shared__ __align__(16) char smem[];
    float* sS    = reinterpret_cast<float*>(smem + OFF_SS);     // [96][81]
    float* sBias = reinterpret_cast<float*>(smem + OFF_BIAS);   // [5120]

    const int tid = threadIdx.x;
    const int wid = tid >> 5, lane = tid & 31;
    const int mt = wid >> 1, nh = wid & 1;
    const int lq = lane >> 2, la = lane & 3;
    const int e0 = blockIdx.x * EBLK;
    const int ne = min(EBLK, E - e0);
    const int r0 = mt * 16 + lq, r1 = r0 + 8;
    const bool v0 = r0 < ne, v1 = r1 < ne;

    fill_W4_async(smem, OFF_W0, WT, 0, tid);
    CP_COMMIT();

    for (int i = tid; i < 5120; i += NTHR) sBias[i] = B2[i];

    if (PASS == 1) {
        for (int idx = tid; idx < EBLK * 64; idx += NTHR) {
            int e = idx >> 6, i = idx & 63;
            float v = 0.0f;
            if (e < ne) {
                int dst = ei[E + e0 + e];
                v = g_h[(size_t)dst * 64 + i];
            }
            sS[e * 81 + i] = v;
        }
    } else {
        for (int idx = tid; idx < EBLK * 80; idx += NTHR) {
            int e = idx / 80, j = idx - e * 80;
            float v = 0.0f;
            if (e < ne) {
                int dst = ei[E + e0 + e];
                float rc = 1.0f / fmaxf(g_cnt[dst], 1.0f);
                const float* he = g_h1 + (size_t)dst * 128;
                if (j < 64) {
                    v = he[j] * rc + g_h[(size_t)dst * 64 + j];
                } else if (j < 72) {
                    int i = j - 64; float p = 0.0f;
#pragma unroll
                    for (int m = 0; m < 3; ++m)
                        p += he[64 + i * 3 + m] * g_shb[(size_t)(e0 + e) * 8 + m];
                    v = p * rc * 0.5773502691896258f;
                } else {
                    int i = j - 72; float p = 0.0f;
#pragma unroll
                    for (int m = 0; m < 5; ++m)
                        p += he[88 + i * 5 + m] * g_shb[(size_t)(e0 + e) * 8 + 3 + m];
                    v = p * rc * 0.4472135954999579f;
                }
            }
            sS[e * 81 + j] = v;
        }
    }

    uint32_t A0[8], A1[8], A2[8], A3[8];
    {
        const uint32_t* u0 = reinterpret_cast<const uint32_t*>(
            Uh + (size_t)(e0 + (v0 ? r0 : 0)) * 128) + la;
        const uint32_t* u1 = reinterpret_cast<const uint32_t*>(
            Uh + (size_t)(e0 + (v1 ? r1 : 0)) * 128) + la;
#pragma unroll
        for (int ks = 0; ks < 8; ++ks) {
            A0[ks] = v0 ? u0[ks * 8]     : 0u;
            A2[ks] = v0 ? u0[ks * 8 + 4] : 0u;
            A1[ks] = v1 ? u1[ks * 8]     : 0u;
            A3[ks] = v1 ? u1[ks * 8 + 4] : 0u;
        }
    }

    float accA[4][4];
    float accB[4], accC[4];
#pragma unroll
    for (int i = 0; i < 4; ++i) {
#pragma unroll
        for (int j = 0; j < 4; ++j) accA[i][j] = 0.0f;
        accB[i] = 0.0f; accC[i] = 0.0f;
    }

    CP_WAIT0();
    __syncthreads();

    for (int qd = 0; qd < 20; ++qd) {
        const char* cur = smem + ((qd & 1) ? OFF_W1 : OFF_W0);
        if (qd + 1 < 20) {
            fill_W4_async(smem, (qd & 1) ? OFF_W0 : OFF_W1, WT, 4 * (qd + 1), tid);
            CP_COMMIT();
        }

#pragma unroll
        for (int sub = 0; sub < 4; ++sub) {
            const int ch = 4 * qd + sub;
            const uint32_t* wb = reinterpret_cast<const uint32_t*>(cur + sub * 16384);

            float c[4][4];
#pragma unroll
            for (int ntl = 0; ntl < 4; ++ntl) {
                const float2 bb = *reinterpret_cast<const float2*>(
                    sBias + ch * 64 + (nh * 4 + ntl) * 8 + la * 2);
                c[ntl][0] = bb.x; c[ntl][1] = bb.y;
                c[ntl][2] = bb.x; c[ntl][3] = bb.y;
            }

            uint32_t bcur[4][2], bnxt[4][2];
#pragma unroll
            for (int ntl = 0; ntl < 4; ++ntl) {
                const int base = ((nh * 4 + ntl) * 8 + lq) * 64;
                bcur[ntl][0] = wb[base + (((0) ^ lq) * 4) + la];
                bcur[ntl][1] = wb[base + (((1) ^ lq) * 4) + la];
            }
#pragma unroll
            for (int ks = 0; ks < 8; ++ks) {
                if (ks < 7) {
#pragma unroll
                    for (int ntl = 0; ntl < 4; ++ntl) {
                        const int base = ((nh * 4 + ntl) * 8 + lq) * 64;
                        bnxt[ntl][0] = wb[base + (((2 * ks + 2) ^ lq) * 4) + la];
                        bnxt[ntl][1] = wb[base + (((2 * ks + 3) ^ lq) * 4) + la];
                    }
                }
#pragma unroll
                for (int ntl = 0; ntl < 4; ++ntl)
                    mma_f16_m16n8k16(c[ntl], A0[ks], A1[ks], A2[ks], A3[ks],
                                     bcur[ntl][0], bcur[ntl][1]);
#pragma unroll
                for (int ntl = 0; ntl < 4; ++ntl) {
                    bcur[ntl][0] = bnxt[ntl][0];
                    bcur[ntl][1] = bnxt[ntl][1];
                }
            }

            if (PASS == 2 || ch < 64) {
                float s0 = sS[r0 * 81 + ch];
                float s1 = sS[r1 * 81 + ch];
#pragma unroll
                for (int ntl = 0; ntl < 4; ++ntl) {
                    accA[ntl][0] = fmaf(s0, c[ntl][0], accA[ntl][0]);
                    accA[ntl][1] = fmaf(s0, c[ntl][1], accA[ntl][1]);
                    accA[ntl][2] = fmaf(s1, c[ntl][2], accA[ntl][2]);
                    accA[ntl][3] = fmaf(s1, c[ntl][3], accA[ntl][3]);
                }
            } else if (ch < 72) {
#pragma unroll
                for (int ntl = 0; ntl < 4; ++ntl) {
                    int i = (ch - 64) * 8 + nh * 4 + ntl;
                    float s0 = sS[r0 * 81 + i];
                    float s1 = sS[r1 * 81 + i];
                    accB[0] = fmaf(s0, c[ntl][0], accB[0]);
                    accB[1] = fmaf(s0, c[ntl][1], accB[1]);
                    accB[2] = fmaf(s1, c[ntl][2], accB[2]);
                    accB[3] = fmaf(s1, c[ntl][3], accB[3]);
                }
            } else {
#pragma unroll
                for (int ntl = 0; ntl < 4; ++ntl) {
                    int i = (ch - 72) * 8 + nh * 4 + ntl;
                    float s0 = sS[r0 * 81 + i];
                    float s1 = sS[r1 * 81 + i];
                    accC[0] = fmaf(s0, c[ntl][0], accC[0]);
                    accC[1] = fmaf(s0, c[ntl][1], accC[1]);
                    accC[2] = fmaf(s1, c[ntl][2], accC[2]);
                    accC[3] = fmaf(s1, c[ntl][3], accC[3]);
                }
            }
        }

        if (qd + 1 < 20) CP_WAIT0();
        __syncthreads();
    }

#pragma unroll
    for (int e = 0; e < 2; ++e) {
        int r = e ? r1 : r0;
        if (r >= ne) continue;
        int src = ei[e0 + r];
        if (PASS == 1) {
            const float C1 = 0.125f;
            float* d1 = g_h1 + (size_t)src * 128;
#pragma unroll
            for (int ntl = 0; ntl < 4; ++ntl) {
                int col = (nh * 4 + ntl) * 8 + la * 2;
                atomicAdd(d1 + col,     C1 * accA[ntl][e * 2]);
                atomicAdd(d1 + col + 1, C1 * accA[ntl][e * 2 + 1]);
            }
            float sh[8];
#pragma unroll
            for (int m = 0; m < 8; ++m) sh[m] = g_shb[(size_t)(e0 + r) * 8 + m];
#pragma unroll
            for (int b = 0; b < 2; ++b) {
                int k = la * 2 + b;
                float a1v = C1 * accB[e * 2 + b];
                float a2v = C1 * accC[e * 2 + b];
#pragma unroll
                for (int m = 0; m < 3; ++m)
                    atomicAdd(d1 + 64 + k * 3 + m, a1v * sh[m]);
#pragma unroll
                for (int m = 0; m < 5; ++m)
                    atomicAdd(d1 + 88 + k * 5 + m, a2v * sh[3 + m]);
            }
            if (nh == 0 && la == 0) atomicAdd(&g_cnt[src], 1.0f);
        } else {
            const float INV = 0.11180339887498948f;  // 1/sqrt(80)
            float* d2 = g_h2 + (size_t)src * 64;
#pragma unroll
            for (int ntl = 0; ntl < 4; ++ntl) {
                int col = (nh * 4 + ntl) * 8 + la * 2;
                atomicAdd(d2 + col,     INV * accA[ntl][e * 2]);
                atomicAdd(d2 + col + 1, INV * accA[ntl][e * 2 + 1]);
            }
        }
    }
}

// ---------------- fused h2 finalize + batch-norm stats ----------------------
__global__ void bn_stats_kernel(int Nn)
{
    __shared__ float rs[256], rs2[256];
    const int c = blockIdx.x;
    float s = 0.0f, s2 = 0.0f;
    for (int n = threadIdx.x; n < Nn; n += 256) {
        float x = g_h2[(size_t)n * 64 + c] / fmaxf(g_cnt[n], 1.0f);
        g_h2[(size_t)n * 64 + c] = x;
        s += x; s2 += x * x;
    }
    rs[threadIdx.x] = s; rs2[threadIdx.x] = s2;
    __syncthreads();
    for (int off = 128; off > 0; off >>= 1) {
        if (threadIdx.x < off) {
            rs[threadIdx.x]  += rs[threadIdx.x + off];
            rs2[threadIdx.x] += rs2[threadIdx.x + off];
        }
        __syncthreads();
    }
    if (threadIdx.x == 0) {
        float mu = rs[0] / (float)Nn;
        g_mu[c]  = mu;
        g_var[c] = rs2[0] / (float)Nn - mu * mu;
    }
}

__global__ void bn_apply_kernel(const float* __restrict__ gamma,
                                const float* __restrict__ beta, int Nn)
{
    int t = blockIdx.x * blockDim.x + threadIdx.x;
    int gs = gridDim.x * blockDim.x;
    for (int idx = t; idx < Nn * 64; idx += gs) {
        int c = idx & 63;
        float x = (g_h2[idx] - g_mu[c]) * rsqrtf(g_var[c] + 1e-5f) * gamma[c] + beta[c];
        g_sphh[idx] = __float2half_rn(softplusf(x));
    }
}

// ---------------- launch ----------------------------------------------------
extern "C" void kernel_launch(void* const* d_in, const int* in_sizes, int n_in,
                              void* d_out, int out_size)
{
    const float* node_feature = (const float*)d_in[0];
    const int*   edge_index   = (const int*)d_in[1];
    const float* edge_feature = (const float*)d_in[2];
    const float* edge_vec     = (const float*)d_in[3];
    const float* w_node = (const float*)d_in[4];
    const float* b_node = (const float*)d_in[5];
    const float* w_skip = (const float*)d_in[6];
    const float* b_skip = (const float*)d_in[7];
    const float* fc1_w1 = (const float*)d_in[8];
    const float* fc1_b1 = (const float*)d_in[9];
    const float* fc1_w2 = (const float*)d_in[10];
    const float* fc1_b2 = (const float*)d_in[11];
    const float* fc2_w1 = (const float*)d_in[12];
    const float* fc2_b1 = (const float*)d_in[13];
    const float* fc2_w2 = (const float*)d_in[14];
    const float* fc2_b2 = (const float*)d_in[15];
    const float* bn_gamma = (const float*)d_in[16];
    const float* bn_beta  = (const float*)d_in[17];
    const float* w_out = (const float*)d_in[18];
    const float* b_out = (const float*)d_in[19];
    float* out = (float*)d_out;

    const int Nn = in_sizes[0] / 256;   // 10000
    const int E  = in_sizes[2] / 128;   // 40000

    float *p_skip, *p_h;
    __half *p_u1h, *p_u2h, *p_w1t, *p_w2t, *p_wt1a, *p_wt1b;
    __half *p_wskt, *p_wndt, *p_wott, *p_sphh;
    cudaGetSymbolAddress((void**)&p_skip, g_skip);
    cudaGetSymbolAddress((void**)&p_h,    g_h);
    cudaGetSymbolAddress((void**)&p_u1h,  g_u1h);
    cudaGetSymbolAddress((void**)&p_u2h,  g_u2h);
    cudaGetSymbolAddress((void**)&p_w1t,  g_w1t);
    cudaGetSymbolAddress((void**)&p_w2t,  g_w2t);
    cudaGetSymbolAddress((void**)&p_wt1a, g_wt1a);
    cudaGetSymbolAddress((void**)&p_wt1b, g_wt1b);
    cudaGetSymbolAddress((void**)&p_wskt, g_wskt);
    cudaGetSymbolAddress((void**)&p_wndt, g_wndt);
    cudaGetSymbolAddress((void**)&p_wott, g_wott);
    cudaGetSymbolAddress((void**)&p_sphh, g_sphh);

    cudaFuncSetAttribute((const void*)msg_mma_kernel<1>,
                         cudaFuncAttributeMaxDynamicSharedMemorySize, SMEM_MSG_B);
    cudaFuncSetAttribute((const void*)msg_mma_kernel<2>,
                         cudaFuncAttributeMaxDynamicSharedMemorySize, SMEM_MSG_B);
    cudaFuncSetAttribute((const void*)mma_gemm<16, 8, 0, 0, 0, 0>,
                         cudaFuncAttributeMaxDynamicSharedMemorySize, 65536);
    cudaFuncSetAttribute((const void*)mma_gemm<16, 4, 0, 0, 0, 0>,
                         cudaFuncAttributeMaxDynamicSharedMemorySize, 32768);
    cudaFuncSetAttribute((const void*)mma_gemm<8, 8, 0, 1, 0, 1>,
                         cudaFuncAttributeMaxDynamicSharedMemorySize, 32768);
    cudaFuncSetAttribute((const void*)mma_gemm<4, 8, 1, 1, 1, 0>,
                         cudaFuncAttributeMaxDynamicSharedMemorySize, 16384);

    // one launch: all weight transposes + sph harmonics + zero buffers
    megaprep_kernel<<<1536, 256>>>(edge_vec, E, Nn,
        fc1_w2, fc2_w2, fc1_w1, fc2_w1, w_skip, w_node, w_out);

    const int mblk = (Nn + 127) / 128;   // 79
    const int ublk = (E + 127) / 128;    // 313

    // skip = node @ w_skip + b  (K=256, N=256)
    mma_gemm<16, 8, 0, 0, 0, 0><<<dim3(mblk, 2), 512, 65536>>>(
        node_feature, p_wskt, b_skip, nullptr, p_skip, Nn, 256);
    // h = node @ w_node + b     (K=256, N=64)
    mma_gemm<16, 4, 0, 0, 0, 0><<<dim3(mblk, 1), 512, 32768>>>(
        node_feature, p_wndt, b_node, nullptr, p_h, Nn, 64);
    // u1/u2 = softplus(edge @ fc_w1 + b) fp16  (K=128, N=128)
    mma_gemm<8, 8, 0, 1, 0, 1><<<dim3(ublk, 1), 512, 32768>>>(
        edge_feature, p_wt1a, fc1_b1, nullptr, p_u1h, E, 128);
    mma_gemm<8, 8, 0, 1, 0, 1><<<dim3(ublk, 1), 512, 32768>>>(
        edge_feature, p_wt1b, fc2_b1, nullptr, p_u2h, E, 128);

    const int nblk = (E + EBLK - 1) / EBLK;
    msg_mma_kernel<1><<<nblk, NTHR, SMEM_MSG_B>>>(edge_index, p_u1h, p_w1t, fc1_b2, E);
    msg_mma_kernel<2><<<nblk, NTHR, SMEM_MSG_B>>>(edge_index, p_u2h, p_w2t, fc2_b2, E);

    bn_stats_kernel<<<64, 256>>>(Nn);
    bn_apply_kernel<<<256, 256>>>(bn_gamma, bn_beta, Nn);

    // out = softplus(sph @ w_out + b_out) + skip  (K=64, N=256)
    mma_gemm<4, 8, 1, 1, 1, 0><<<dim3(mblk, 2), 512, 16384>>>(
        p_sphh, p_wott, b_out, p_skip, out, Nn, 256);
}

// round 14
// speedup vs baseline: 1.9394x; 1.0568x over previous
#include <cuda_runtime.h>
#include <cuda_fp16.h>
#include <math.h>
#include <stdint.h>

// Problem constants: N=10000, E=40000, IN_CH=256, OUT_CH=256,
// EDGE_DIM=128, NS=64, NV=8, WN1=WN2=5120.

#define MAXN 10000
#define MAXE 40000

// ---------------- scratch (static __device__ — no allocations allowed) -----
__device__ float  g_skip[MAXN * 256];
__device__ float  g_h   [MAXN * 64];
__device__ __half g_u1h [MAXE * 128];
__device__ __half g_u2h [MAXE * 128];
__device__ float  g_shb [MAXE * 8];     // sh1 (3) + sh2 (5)
__device__ float  g_h1  [MAXN * 128];   // RAW msg1 sums (finalized inline in msg2)
__device__ float  g_cnt [MAXN];
__device__ float  g_h2  [MAXN * 64];
__device__ float  g_mu  [64];           // BN sum accumulators (atomic)
__device__ float  g_var [64];
__device__ __half g_sphh[MAXN * 64];    // softplus(bn) as fp16 for out-GEMM
__device__ __half g_w1t [5120 * 128];   // fc1_w2^T fp16
__device__ __half g_w2t [5120 * 128];   // fc2_w2^T fp16
__device__ __half g_wt1a[128 * 128];    // fc1_w1^T fp16
__device__ __half g_wt1b[128 * 128];    // fc2_w1^T fp16
__device__ __half g_wskt[256 * 256];    // w_skip^T fp16
__device__ __half g_wndt[64 * 256];     // w_node^T fp16
__device__ __half g_wott[256 * 64];     // w_out^T  fp16

__device__ __forceinline__ float softplusf(float x) {
    return fmaxf(x, 0.0f) + log1pf(expf(-fabsf(x)));
}
__device__ __forceinline__ uint32_t smem_u32(const void* p) {
    uint32_t a;
    asm("{ .reg .u64 t; cvta.to.shared.u64 t, %1; cvt.u32.u64 %0, t; }"
        : "=r"(a) : "l"(p));
    return a;
}
__device__ __forceinline__ uint32_t pack_h2(float x, float y) {
    __half2 h = __floats2half2_rn(x, y);
    return *reinterpret_cast<uint32_t*>(&h);
}
__device__ __forceinline__ void mma_f16_m16n8k16(float c[4],
    uint32_t a0, uint32_t a1, uint32_t a2, uint32_t a3,
    uint32_t b0, uint32_t b1)
{
    asm volatile(
        "mma.sync.aligned.m16n8k16.row.col.f32.f16.f16.f32 "
        "{%0,%1,%2,%3}, {%4,%5,%6,%7}, {%8,%9}, {%0,%1,%2,%3};"
        : "+f"(c[0]), "+f"(c[1]), "+f"(c[2]), "+f"(c[3])
        : "r"(a0), "r"(a1), "r"(a2), "r"(a3), "r"(b0), "r"(b1));
}
#define CP_ASYNC16(dst, src) \
    asm volatile("cp.async.cg.shared.global [%0], [%1], 16;" :: "r"(dst), "l"(src))
#define CP_COMMIT()  asm volatile("cp.async.commit_group;" ::: "memory")
#define CP_WAIT0()   asm volatile("cp.async.wait_group 0;" ::: "memory")

// ======================= mega-prep: all transposes + sh + zero ==============
__device__ __forceinline__ void ttile(float (*t)[33],
    const float* __restrict__ W, __half* __restrict__ WT,
    int K, int N, int bx, int by, int tx, int ty)
{
    const int n0 = bx * 32, k0 = by * 32;
    for (int r = ty; r < 32; r += 8)
        t[r][tx] = W[(size_t)(k0 + r) * N + n0 + tx];
    __syncthreads();
    for (int r = ty; r < 32; r += 8)
        WT[(size_t)(n0 + r) * K + k0 + tx] = __float2half_rn(t[tx][r]);
}

__global__ void __launch_bounds__(256) megaprep_kernel(
    const float* __restrict__ ev, int E, int Nn,
    const float* __restrict__ fc1w2, const float* __restrict__ fc2w2,
    const float* __restrict__ fc1w1, const float* __restrict__ fc2w1,
    const float* __restrict__ wskip, const float* __restrict__ wnode,
    const float* __restrict__ wout)
{
    __shared__ float t[32][33];
    const int tx = threadIdx.x & 31, ty = threadIdx.x >> 5;
    int b = blockIdx.x;
    if (b < 640)  { ttile(t, fc1w2, g_w1t, 128, 5120, b % 160, b / 160, tx, ty); return; }
    b -= 640;
    if (b < 640)  { ttile(t, fc2w2, g_w2t, 128, 5120, b % 160, b / 160, tx, ty); return; }
    b -= 640;
    if (b < 16)   { ttile(t, fc1w1, g_wt1a, 128, 128, b % 4, b / 4, tx, ty); return; }
    b -= 16;
    if (b < 16)   { ttile(t, fc2w1, g_wt1b, 128, 128, b % 4, b / 4, tx, ty); return; }
    b -= 16;
    if (b < 64)   { ttile(t, wskip, g_wskt, 256, 256, b % 8, b / 8, tx, ty); return; }
    b -= 64;
    if (b < 16)   { ttile(t, wnode, g_wndt, 256, 64, b % 2, b / 2, tx, ty); return; }
    b -= 16;
    if (b < 16)   { ttile(t, wout, g_wott, 64, 256, b % 8, b / 8, tx, ty); return; }
    b -= 16;
    // sh + zero
    const int tid = b * 256 + threadIdx.x;
    const int gs = 128 * 256;
    for (int e = tid; e < E; e += gs) {
        float x = ev[e * 3 + 0], y = ev[e * 3 + 1], z = ev[e * 3 + 2];
        float rn = rsqrtf(x * x + y * y + z * z);
        x *= rn; y *= rn; z *= rn;
        const float s3 = 1.7320508075688772f;
        const float s5 = 2.2360679774997896f;
        float* o = g_shb + (size_t)e * 8;
        o[0] = s3 * x;
        o[1] = s3 * y;
        o[2] = s3 * z;
        o[3] = s5 * s3 * x * z;
        o[4] = s5 * s3 * x * y;
        o[5] = s5 * (y * y - 0.5f * (x * x + z * z));
        o[6] = s5 * s3 * y * z;
        o[7] = s5 * (s3 * 0.5f) * (z * z - x * x);
    }
    for (int i = tid; i < Nn * 128; i += gs) g_h1[i] = 0.0f;
    for (int i = tid; i < Nn * 64;  i += gs) g_h2[i] = 0.0f;
    for (int i = tid; i < Nn;       i += gs) g_cnt[i] = 0.0f;
    if (tid < 64) { g_mu[tid] = 0.0f; g_var[tid] = 0.0f; }
}

// ======================= unified fp16 MMA GEMM ===============================
// Out[M, Ntot] = epi(A[M, K=KS*16] @ WT^T + bias [+ addsrc]).
// 256 thr, 8 warps: mt = wid>>1 (64 rows/CTA), nh = wid&1; warp covers NT
// n-tiles of 8 -> CTA N = NT*16. grid = (ceil(M/64), Ntot/(NT*16)).
// MINB=2 for small KS gives 2 CTAs/SM (latency hiding across tail waves).
template <int KS, int NT, int AHALF, int ACT, int ADD, int OUTH, int MINB>
__global__ void __launch_bounds__(256, MINB) mma_gemm(
    const void* __restrict__ Av, const __half* __restrict__ WT,
    const float* __restrict__ bias, const float* __restrict__ addsrc,
    void* __restrict__ Outv, int M, int Ntot)
{
    constexpr int K = KS * 16;
    constexpr int CTAN = NT * 16;
    constexpr int ROWW = KS * 8;      // uint32 words per W smem row
    extern __shared__ __align__(16) char ws[];
    const int tid = threadIdx.x;
    const int wid = tid >> 5, lane = tid & 31;
    const int mt = wid >> 1, nh = wid & 1;
    const int lq = lane >> 2, la = lane & 3;
    const int bn0 = blockIdx.y * CTAN;

    for (int idx = tid; idx < CTAN * KS * 2; idx += 256) {
        int row = idx / (KS * 2);
        int q   = idx - row * (KS * 2);
        const __half* src = WT + (size_t)(bn0 + row) * K + q * 8;
        uint32_t dst = smem_u32(ws + row * (KS * 32) + ((q ^ (row & 7)) * 16));
        CP_ASYNC16(dst, src);
    }
    CP_COMMIT();

    const int r0 = blockIdx.x * 64 + mt * 16 + lq;
    const int r1 = r0 + 8;
    const bool v0 = r0 < M, v1 = r1 < M;

    uint32_t A0[KS], A1[KS], A2[KS], A3[KS];
    if (AHALF) {
        const uint32_t* u0 = reinterpret_cast<const uint32_t*>(
            (const __half*)Av + (size_t)(v0 ? r0 : 0) * K) + la;
        const uint32_t* u1 = reinterpret_cast<const uint32_t*>(
            (const __half*)Av + (size_t)(v1 ? r1 : 0) * K) + la;
#pragma unroll
        for (int ks = 0; ks < KS; ++ks) {
            A0[ks] = v0 ? u0[ks * 8]     : 0u;
            A2[ks] = v0 ? u0[ks * 8 + 4] : 0u;
            A1[ks] = v1 ? u1[ks * 8]     : 0u;
            A3[ks] = v1 ? u1[ks * 8 + 4] : 0u;
        }
    } else {
        const float* a0p = (const float*)Av + (size_t)(v0 ? r0 : 0) * K + 2 * la;
        const float* a1p = (const float*)Av + (size_t)(v1 ? r1 : 0) * K + 2 * la;
#pragma unroll
        for (int ks = 0; ks < KS; ++ks) {
            float2 f0 = *reinterpret_cast<const float2*>(a0p + ks * 16);
            float2 f2 = *reinterpret_cast<const float2*>(a0p + ks * 16 + 8);
            float2 f1 = *reinterpret_cast<const float2*>(a1p + ks * 16);
            float2 f3 = *reinterpret_cast<const float2*>(a1p + ks * 16 + 8);
            A0[ks] = v0 ? pack_h2(f0.x, f0.y) : 0u;
            A2[ks] = v0 ? pack_h2(f2.x, f2.y) : 0u;
            A1[ks] = v1 ? pack_h2(f1.x, f1.y) : 0u;
            A3[ks] = v1 ? pack_h2(f3.x, f3.y) : 0u;
        }
    }

    float c[NT][4];
#pragma unroll
    for (int nt = 0; nt < NT; ++nt) {
        float2 bb = __ldg(reinterpret_cast<const float2*>(
            bias + bn0 + (nh * NT + nt) * 8 + la * 2));
        c[nt][0] = bb.x; c[nt][1] = bb.y;
        c[nt][2] = bb.x; c[nt][3] = bb.y;
    }

    CP_WAIT0();
    __syncthreads();
    const uint32_t* wb = reinterpret_cast<const uint32_t*>(ws);
#pragma unroll
    for (int ks = 0; ks < KS; ++ks) {
#pragma unroll
        for (int nt = 0; nt < NT; ++nt) {
            const int base = ((nh * NT + nt) * 8 + lq) * ROWW;
            uint32_t b0 = wb[base + (((2 * ks)     ^ lq) * 4) + la];
            uint32_t b1 = wb[base + (((2 * ks + 1) ^ lq) * 4) + la];
            mma_f16_m16n8k16(c[nt], A0[ks], A1[ks], A2[ks], A3[ks], b0, b1);
        }
    }

#pragma unroll
    for (int nt = 0; nt < NT; ++nt) {
        const int gcol = bn0 + (nh * NT + nt) * 8 + la * 2;
#pragma unroll
        for (int e = 0; e < 2; ++e) {
            int r = e ? r1 : r0;
            if (e ? !v1 : !v0) continue;
            float x0 = c[nt][e * 2], x1 = c[nt][e * 2 + 1];
            if (ACT) { x0 = softplusf(x0); x1 = softplusf(x1); }
            if (ADD) {
                float2 ad = *reinterpret_cast<const float2*>(
                    addsrc + (size_t)r * Ntot + gcol);
                x0 += ad.x; x1 += ad.y;
            }
            if (OUTH) {
                *reinterpret_cast<__half2*>((__half*)Outv + (size_t)r * Ntot + gcol) =
                    __floats2half2_rn(x0, x1);
            } else {
                *reinterpret_cast<float2*>((float*)Outv + (size_t)r * Ntot + gcol) =
                    make_float2(x0, x1);
            }
        }
    }
}

// ======================= fp16 mma.sync fused message pass ====================
// (unchanged — proven config)
#define EBLK     96
#define NTHR     384
#define OFF_W0   0
#define OFF_W1   65536
#define OFF_SS   131072
#define OFF_BIAS 162176
#define SMEM_MSG_B 182656

__device__ __forceinline__ void fill_W4_async(char* smem, uint32_t bufoff,
    const __half* __restrict__ WT, int ch0, int tid)
{
    for (int idx = tid; idx < 4096; idx += NTHR) {
        int sub = idx >> 10;
        int w   = idx & 1023;
        int row = w >> 4;
        int q   = w & 15;
        const __half* src = WT + ((size_t)(ch0 + sub) * 64 + row) * 128 + q * 8;
        uint32_t dst = smem_u32(smem + bufoff + sub * 16384 +
                                row * 256 + ((q ^ (row & 7)) * 16));
        CP_ASYNC16(dst, src);
    }
}

template <int PASS>
__global__ void __launch_bounds__(NTHR, 1) msg_mma_kernel(
    const int* __restrict__ ei, const __half* __restrict__ Uh,
    const __half* __restrict__ WT, const float* __restrict__ B2, int E)
{
    extern __shared__ __align__(16) char smem[];
    float* sS    = reinterpret_cast<float*>(smem + OFF_SS);     // [96][81]
    float* sBias = reinterpret_cast<float*>(smem + OFF_BIAS);   // [5120]

    const int tid = threadIdx.x;
    const int wid = tid >> 5, lane = tid & 31;
    const int mt = wid >> 1, nh = wid & 1;
    const int lq = lane >> 2, la = lane & 3;
    const int e0 = blockIdx.x * EBLK;
    const int ne = min(EBLK, E - e0);
    const int r0 = mt * 16 + lq, r1 = r0 + 8;
    const bool v0 = r0 < ne, v1 = r1 < ne;

    fill_W4_async(smem, OFF_W0, WT, 0, tid);
    CP_COMMIT();

    for (int i = tid; i < 5120; i += NTHR) sBias[i] = B2[i];

    if (PASS == 1) {
        for (int idx = tid; idx < EBLK * 64; idx += NTHR) {
            int e = idx >> 6, i = idx & 63;
            float v = 0.0f;
            if (e < ne) {
                int dst = ei[E + e0 + e];
                v = g_h[(size_t)dst * 64 + i];
            }
            sS[e * 81 + i] = v;
        }
    } else {
        for (int idx = tid; idx < EBLK * 80; idx += NTHR) {
            int e = idx / 80, j = idx - e * 80;
            float v = 0.0f;
            if (e < ne) {
                int dst = ei[E + e0 + e];
                float rc = 1.0f / fmaxf(g_cnt[dst], 1.0f);
                const float* he = g_h1 + (size_t)dst * 128;
                if (j < 64) {
                    v = he[j] * rc + g_h[(size_t)dst * 64 + j];
                } else if (j < 72) {
                    int i = j - 64; float p = 0.0f;
#pragma unroll
                    for (int m = 0; m < 3; ++m)
                        p += he[64 + i * 3 + m] * g_shb[(size_t)(e0 + e) * 8 + m];
                    v = p * rc * 0.5773502691896258f;
                } else {
                    int i = j - 72; float p = 0.0f;
#pragma unroll
                    for (int m = 0; m < 5; ++m)
                        p += he[88 + i * 5 + m] * g_shb[(size_t)(e0 + e) * 8 + 3 + m];
                    v = p * rc * 0.4472135954999579f;
                }
            }
            sS[e * 81 + j] = v;
        }
    }

    uint32_t A0[8], A1[8], A2[8], A3[8];
    {
        const uint32_t* u0 = reinterpret_cast<const uint32_t*>(
            Uh + (size_t)(e0 + (v0 ? r0 : 0)) * 128) + la;
        const uint32_t* u1 = reinterpret_cast<const uint32_t*>(
            Uh + (size_t)(e0 + (v1 ? r1 : 0)) * 128) + la;
#pragma unroll
        for (int ks = 0; ks < 8; ++ks) {
            A0[ks] = v0 ? u0[ks * 8]     : 0u;
            A2[ks] = v0 ? u0[ks * 8 + 4] : 0u;
            A1[ks] = v1 ? u1[ks * 8]     : 0u;
            A3[ks] = v1 ? u1[ks * 8 + 4] : 0u;
        }
    }

    float accA[4][4];
    float accB[4], accC[4];
#pragma unroll
    for (int i = 0; i < 4; ++i) {
#pragma unroll
        for (int j = 0; j < 4; ++j) accA[i][j] = 0.0f;
        accB[i] = 0.0f; accC[i] = 0.0f;
    }

    CP_WAIT0();
    __syncthreads();

    for (int qd = 0; qd < 20; ++qd) {
        const char* cur = smem + ((qd & 1) ? OFF_W1 : OFF_W0);
        if (qd + 1 < 20) {
            fill_W4_async(smem, (qd & 1) ? OFF_W0 : OFF_W1, WT, 4 * (qd + 1), tid);
            CP_COMMIT();
        }

#pragma unroll
        for (int sub = 0; sub < 4; ++sub) {
            const int ch = 4 * qd + sub;
            const uint32_t* wb = reinterpret_cast<const uint32_t*>(cur + sub * 16384);

            float c[4][4];
#pragma unroll
            for (int ntl = 0; ntl < 4; ++ntl) {
                const float2 bb = *reinterpret_cast<const float2*>(
                    sBias + ch * 64 + (nh * 4 + ntl) * 8 + la * 2);
                c[ntl][0] = bb.x; c[ntl][1] = bb.y;
                c[ntl][2] = bb.x; c[ntl][3] = bb.y;
            }

            uint32_t bcur[4][2], bnxt[4][2];
#pragma unroll
            for (int ntl = 0; ntl < 4; ++ntl) {
                const int base = ((nh * 4 + ntl) * 8 + lq) * 64;
                bcur[ntl][0] = wb[base + (((0) ^ lq) * 4) + la];
                bcur[ntl][1] = wb[base + (((1) ^ lq) * 4) + la];
            }
#pragma unroll
            for (int ks = 0; ks < 8; ++ks) {
                if (ks < 7) {
#pragma unroll
                    for (int ntl = 0; ntl < 4; ++ntl) {
                        const int base = ((nh * 4 + ntl) * 8 + lq) * 64;
                        bnxt[ntl][0] = wb[base + (((2 * ks + 2) ^ lq) * 4) + la];
                        bnxt[ntl][1] = wb[base + (((2 * ks + 3) ^ lq) * 4) + la];
                    }
                }
#pragma unroll
                for (int ntl = 0; ntl < 4; ++ntl)
                    mma_f16_m16n8k16(c[ntl], A0[ks], A1[ks], A2[ks], A3[ks],
                                     bcur[ntl][0], bcur[ntl][1]);
#pragma unroll
                for (int ntl = 0; ntl < 4; ++ntl) {
                    bcur[ntl][0] = bnxt[ntl][0];
                    bcur[ntl][1] = bnxt[ntl][1];
                }
            }

            if (PASS == 2 || ch < 64) {
                float s0 = sS[r0 * 81 + ch];
                float s1 = sS[r1 * 81 + ch];
#pragma unroll
                for (int ntl = 0; ntl < 4; ++ntl) {
                    accA[ntl][0] = fmaf(s0, c[ntl][0], accA[ntl][0]);
                    accA[ntl][1] = fmaf(s0, c[ntl][1], accA[ntl][1]);
                    accA[ntl][2] = fmaf(s1, c[ntl][2], accA[ntl][2]);
                    accA[ntl][3] = fmaf(s1, c[ntl][3], accA[ntl][3]);
                }
            } else if (ch < 72) {
#pragma unroll
                for (int ntl = 0; ntl < 4; ++ntl) {
                    int i = (ch - 64) * 8 + nh * 4 + ntl;
                    float s0 = sS[r0 * 81 + i];
                    float s1 = sS[r1 * 81 + i];
                    accB[0] = fmaf(s0, c[ntl][0], accB[0]);
                    accB[1] = fmaf(s0, c[ntl][1], accB[1]);
                    accB[2] = fmaf(s1, c[ntl][2], accB[2]);
                    accB[3] = fmaf(s1, c[ntl][3], accB[3]);
                }
            } else {
#pragma unroll
                for (int ntl = 0; ntl < 4; ++ntl) {
                    int i = (ch - 72) * 8 + nh * 4 + ntl;
                    float s0 = sS[r0 * 81 + i];
                    float s1 = sS[r1 * 81 + i];
                    accC[0] = fmaf(s0, c[ntl][0], accC[0]);
                    accC[1] = fmaf(s0, c[ntl][1], accC[1]);
                    accC[2] = fmaf(s1, c[ntl][2], accC[2]);
                    accC[3] = fmaf(s1, c[ntl][3], accC[3]);
                }
            }
        }

        if (qd + 1 < 20) CP_WAIT0();
        __syncthreads();
    }

#pragma unroll
    for (int e = 0; e < 2; ++e) {
        int r = e ? r1 : r0;
        if (r >= ne) continue;
        int src = ei[e0 + r];
        if (PASS == 1) {
            const float C1 = 0.125f;
            float* d1 = g_h1 + (size_t)src * 128;
#pragma unroll
            for (int ntl = 0; ntl < 4; ++ntl) {
                int col = (nh * 4 + ntl) * 8 + la * 2;
                atomicAdd(d1 + col,     C1 * accA[ntl][e * 2]);
                atomicAdd(d1 + col + 1, C1 * accA[ntl][e * 2 + 1]);
            }
            float sh[8];
#pragma unroll
            for (int m = 0; m < 8; ++m) sh[m] = g_shb[(size_t)(e0 + r) * 8 + m];
#pragma unroll
            for (int b = 0; b < 2; ++b) {
                int k = la * 2 + b;
                float a1v = C1 * accB[e * 2 + b];
                float a2v = C1 * accC[e * 2 + b];
#pragma unroll
                for (int m = 0; m < 3; ++m)
                    atomicAdd(d1 + 64 + k * 3 + m, a1v * sh[m]);
#pragma unroll
                for (int m = 0; m < 5; ++m)
                    atomicAdd(d1 + 88 + k * 5 + m, a2v * sh[3 + m]);
            }
            if (nh == 0 && la == 0) atomicAdd(&g_cnt[src], 1.0f);
        } else {
            const float INV = 0.11180339887498948f;  // 1/sqrt(80)
            float* d2 = g_h2 + (size_t)src * 64;
#pragma unroll
            for (int ntl = 0; ntl < 4; ++ntl) {
                int col = (nh * 4 + ntl) * 8 + la * 2;
                atomicAdd(d2 + col,     INV * accA[ntl][e * 2]);
                atomicAdd(d2 + col + 1, INV * accA[ntl][e * 2 + 1]);
            }
        }
    }
}

// ---------------- coalesced h2 finalize + BN reduce --------------------------
// 148 blocks x 256 thr. thread = (rowgrp = tid>>6, c = tid&63); 4 rows/iter,
// fully coalesced 1KB reads. Per-block reduce then atomicAdd into g_mu/g_var.
__global__ void __launch_bounds__(256) bn_reduce_kernel(int Nn)
{
    __shared__ float ss[4][64], ss2[4][64];
    const int c = threadIdx.x & 63, g = threadIdx.x >> 6;
    float s = 0.0f, s2 = 0.0f;
    for (int base = blockIdx.x * 4; base < Nn; base += gridDim.x * 4) {
        int n = base + g;
        if (n < Nn) {
            float x = g_h2[(size_t)n * 64 + c] / fmaxf(g_cnt[n], 1.0f);
            g_h2[(size_t)n * 64 + c] = x;
            s += x; s2 += x * x;
        }
    }
    ss[g][c] = s; ss2[g][c] = s2;
    __syncthreads();
    if (g == 0) {
        float ts = ss[0][c] + ss[1][c] + ss[2][c] + ss[3][c];
        float ts2 = ss2[0][c] + ss2[1][c] + ss2[2][c] + ss2[3][c];
        atomicAdd(&g_mu[c], ts);
        atomicAdd(&g_var[c], ts2);
    }
}

__global__ void bn_apply_kernel(const float* __restrict__ gamma,
                                const float* __restrict__ beta, int Nn)
{
    int t = blockIdx.x * blockDim.x + threadIdx.x;
    int gs = gridDim.x * blockDim.x;
    const float invN = 1.0f / (float)Nn;
    for (int idx = t; idx < Nn * 64; idx += gs) {
        int c = idx & 63;
        float mu = g_mu[c] * invN;
        float var = g_var[c] * invN - mu * mu;
        float x = (g_h2[idx] - mu) * rsqrtf(var + 1e-5f) * gamma[c] + beta[c];
        g_sphh[idx] = __float2half_rn(softplusf(x));
    }
}

// ---------------- launch ----------------------------------------------------
extern "C" void kernel_launch(void* const* d_in, const int* in_sizes, int n_in,
                              void* d_out, int out_size)
{
    const float* node_feature = (const float*)d_in[0];
    const int*   edge_index   = (const int*)d_in[1];
    const float* edge_feature = (const float*)d_in[2];
    const float* edge_vec     = (const float*)d_in[3];
    const float* w_node = (const float*)d_in[4];
    const float* b_node = (const float*)d_in[5];
    const float* w_skip = (const float*)d_in[6];
    const float* b_skip = (const float*)d_in[7];
    const float* fc1_w1 = (const float*)d_in[8];
    const float* fc1_b1 = (const float*)d_in[9];
    const float* fc1_w2 = (const float*)d_in[10];
    const float* fc1_b2 = (const float*)d_in[11];
    const float* fc2_w1 = (const float*)d_in[12];
    const float* fc2_b1 = (const float*)d_in[13];
    const float* fc2_w2 = (const float*)d_in[14];
    const float* fc2_b2 = (const float*)d_in[15];
    const float* bn_gamma = (const float*)d_in[16];
    const float* bn_beta  = (const float*)d_in[17];
    const float* w_out = (const float*)d_in[18];
    const float* b_out = (const float*)d_in[19];
    float* out = (float*)d_out;

    const int Nn = in_sizes[0] / 256;   // 10000
    const int E  = in_sizes[2] / 128;   // 40000

    float *p_skip, *p_h;
    __half *p_u1h, *p_u2h, *p_w1t, *p_w2t, *p_wt1a, *p_wt1b;
    __half *p_wskt, *p_wndt, *p_wott, *p_sphh;
    cudaGetSymbolAddress((void**)&p_skip, g_skip);
    cudaGetSymbolAddress((void**)&p_h,    g_h);
    cudaGetSymbolAddress((void**)&p_u1h,  g_u1h);
    cudaGetSymbolAddress((void**)&p_u2h,  g_u2h);
    cudaGetSymbolAddress((void**)&p_w1t,  g_w1t);
    cudaGetSymbolAddress((void**)&p_w2t,  g_w2t);
    cudaGetSymbolAddress((void**)&p_wt1a, g_wt1a);
    cudaGetSymbolAddress((void**)&p_wt1b, g_wt1b);
    cudaGetSymbolAddress((void**)&p_wskt, g_wskt);
    cudaGetSymbolAddress((void**)&p_wndt, g_wndt);
    cudaGetSymbolAddress((void**)&p_wott, g_wott);
    cudaGetSymbolAddress((void**)&p_sphh, g_sphh);

    cudaFuncSetAttribute((const void*)msg_mma_kernel<1>,
                         cudaFuncAttributeMaxDynamicSharedMemorySize, SMEM_MSG_B);
    cudaFuncSetAttribute((const void*)msg_mma_kernel<2>,
                         cudaFuncAttributeMaxDynamicSharedMemorySize, SMEM_MSG_B);
    cudaFuncSetAttribute((const void*)mma_gemm<16, 8, 0, 0, 0, 0, 1>,
                         cudaFuncAttributeMaxDynamicSharedMemorySize, 65536);
    cudaFuncSetAttribute((const void*)mma_gemm<16, 4, 0, 0, 0, 0, 1>,
                         cudaFuncAttributeMaxDynamicSharedMemorySize, 32768);
    cudaFuncSetAttribute((const void*)mma_gemm<8, 8, 0, 1, 0, 1, 2>,
                         cudaFuncAttributeMaxDynamicSharedMemorySize, 32768);
    cudaFuncSetAttribute((const void*)mma_gemm<4, 8, 1, 1, 1, 0, 2>,
                         cudaFuncAttributeMaxDynamicSharedMemorySize, 16384);

    // one launch: all weight transposes + sph harmonics + zero buffers
    megaprep_kernel<<<1536, 256>>>(edge_vec, E, Nn,
        fc1_w2, fc2_w2, fc1_w1, fc2_w1, w_skip, w_node, w_out);

    const int mblk = (Nn + 63) / 64;   // 157
    const int ublk = (E + 63) / 64;    // 625

    // skip = node @ w_skip + b  (K=256, N=256)
    mma_gemm<16, 8, 0, 0, 0, 0, 1><<<dim3(mblk, 2), 256, 65536>>>(
        node_feature, p_wskt, b_skip, nullptr, p_skip, Nn, 256);
    // h = node @ w_node + b     (K=256, N=64)
    mma_gemm<16, 4, 0, 0, 0, 0, 1><<<dim3(mblk, 1), 256, 32768>>>(
        node_feature, p_wndt, b_node, nullptr, p_h, Nn, 64);
    // u1/u2 = softplus(edge @ fc_w1 + b) fp16  (K=128, N=128)
    mma_gemm<8, 8, 0, 1, 0, 1, 2><<<dim3(ublk, 1), 256, 32768>>>(
        edge_feature, p_wt1a, fc1_b1, nullptr, p_u1h, E, 128);
    mma_gemm<8, 8, 0, 1, 0, 1, 2><<<dim3(ublk, 1), 256, 32768>>>(
        edge_feature, p_wt1b, fc2_b1, nullptr, p_u2h, E, 128);

    const int nblk = (E + EBLK - 1) / EBLK;
    msg_mma_kernel<1><<<nblk, NTHR, SMEM_MSG_B>>>(edge_index, p_u1h, p_w1t, fc1_b2, E);
    msg_mma_kernel<2><<<nblk, NTHR, SMEM_MSG_B>>>(edge_index, p_u2h, p_w2t, fc2_b2, E);

    bn_reduce_kernel<<<148, 256>>>(Nn);
    bn_apply_kernel<<<256, 256>>>(bn_gamma, bn_beta, Nn);

    // out = softplus(sph @ w_out + b_out) + skip  (K=64, N=256)
    mma_gemm<4, 8, 1, 1, 1, 0, 2><<<dim3(mblk, 2), 256, 16384>>>(
        p_sphh, p_wott, b_out, p_skip, out, Nn, 256);
}

// round 15
// speedup vs baseline: 1.9420x; 1.0013x over previous
#include <cuda_runtime.h>
#include <cuda_fp16.h>
#include <math.h>
#include <stdint.h>

// Problem constants: N=10000, E=40000, IN_CH=256, OUT_CH=256,
// EDGE_DIM=128, NS=64, NV=8, WN1=WN2=5120.

#define MAXN 10000
#define MAXE 40000

// ---------------- scratch (static __device__ — no allocations allowed) -----
__device__ float  g_skip[MAXN * 256];
__device__ float  g_h   [MAXN * 64];
__device__ __half g_u1h [MAXE * 128];
__device__ __half g_u2h [MAXE * 128];
__device__ float  g_shb [MAXE * 8];     // sh1 (3) + sh2 (5)
__device__ float  g_h1  [MAXN * 128];   // RAW msg1 sums (finalized inline in msg2)
__device__ float  g_cnt [MAXN];
__device__ float  g_h2  [MAXN * 64];
__device__ float  g_mu  [64];           // BN sum accumulators (atomic)
__device__ float  g_var [64];
__device__ __half g_w1t [5120 * 128];   // fc1_w2^T fp16
__device__ __half g_w2t [5120 * 128];   // fc2_w2^T fp16
__device__ __half g_wt1a[128 * 128];    // fc1_w1^T fp16
__device__ __half g_wt1b[128 * 128];    // fc2_w1^T fp16
__device__ __half g_wskt[256 * 256];    // w_skip^T fp16
__device__ __half g_wndt[64 * 256];     // w_node^T fp16
__device__ __half g_wott[256 * 64];     // w_out^T  fp16

__device__ __forceinline__ float softplusf(float x) {
    return fmaxf(x, 0.0f) + log1pf(expf(-fabsf(x)));
}
__device__ __forceinline__ uint32_t smem_u32(const void* p) {
    uint32_t a;
    asm("{ .reg .u64 t; cvta.to.shared.u64 t, %1; cvt.u32.u64 %0, t; }"
        : "=r"(a) : "l"(p));
    return a;
}
__device__ __forceinline__ uint32_t pack_h2(float x, float y) {
    __half2 h = __floats2half2_rn(x, y);
    return *reinterpret_cast<uint32_t*>(&h);
}
__device__ __forceinline__ void mma_f16_m16n8k16(float c[4],
    uint32_t a0, uint32_t a1, uint32_t a2, uint32_t a3,
    uint32_t b0, uint32_t b1)
{
    asm volatile(
        "mma.sync.aligned.m16n8k16.row.col.f32.f16.f16.f32 "
        "{%0,%1,%2,%3}, {%4,%5,%6,%7}, {%8,%9}, {%0,%1,%2,%3};"
        : "+f"(c[0]), "+f"(c[1]), "+f"(c[2]), "+f"(c[3])
        : "r"(a0), "r"(a1), "r"(a2), "r"(a3), "r"(b0), "r"(b1));
}
#define CP_ASYNC16(dst, src) \
    asm volatile("cp.async.cg.shared.global [%0], [%1], 16;" :: "r"(dst), "l"(src))
#define CP_COMMIT()  asm volatile("cp.async.commit_group;" ::: "memory")
#define CP_WAIT0()   asm volatile("cp.async.wait_group 0;" ::: "memory")

// ======================= mega-prep: all transposes + sh + zero ==============
__device__ __forceinline__ void ttile(float (*t)[33],
    const float* __restrict__ W, __half* __restrict__ WT,
    int K, int N, int bx, int by, int tx, int ty)
{
    const int n0 = bx * 32, k0 = by * 32;
    for (int r = ty; r < 32; r += 8)
        t[r][tx] = W[(size_t)(k0 + r) * N + n0 + tx];
    __syncthreads();
    for (int r = ty; r < 32; r += 8)
        WT[(size_t)(n0 + r) * K + k0 + tx] = __float2half_rn(t[tx][r]);
}

__global__ void __launch_bounds__(256) megaprep_kernel(
    const float* __restrict__ ev, int E, int Nn,
    const float* __restrict__ fc1w2, const float* __restrict__ fc2w2,
    const float* __restrict__ fc1w1, const float* __restrict__ fc2w1,
    const float* __restrict__ wskip, const float* __restrict__ wnode,
    const float* __restrict__ wout)
{
    __shared__ float t[32][33];
    const int tx = threadIdx.x & 31, ty = threadIdx.x >> 5;
    int b = blockIdx.x;
    if (b < 640)  { ttile(t, fc1w2, g_w1t, 128, 5120, b % 160, b / 160, tx, ty); return; }
    b -= 640;
    if (b < 640)  { ttile(t, fc2w2, g_w2t, 128, 5120, b % 160, b / 160, tx, ty); return; }
    b -= 640;
    if (b < 16)   { ttile(t, fc1w1, g_wt1a, 128, 128, b % 4, b / 4, tx, ty); return; }
    b -= 16;
    if (b < 16)   { ttile(t, fc2w1, g_wt1b, 128, 128, b % 4, b / 4, tx, ty); return; }
    b -= 16;
    if (b < 64)   { ttile(t, wskip, g_wskt, 256, 256, b % 8, b / 8, tx, ty); return; }
    b -= 64;
    if (b < 16)   { ttile(t, wnode, g_wndt, 256, 64, b % 2, b / 2, tx, ty); return; }
    b -= 16;
    if (b < 16)   { ttile(t, wout, g_wott, 64, 256, b % 8, b / 8, tx, ty); return; }
    b -= 16;
    // sh + zero
    const int tid = b * 256 + threadIdx.x;
    const int gs = 128 * 256;
    for (int e = tid; e < E; e += gs) {
        float x = ev[e * 3 + 0], y = ev[e * 3 + 1], z = ev[e * 3 + 2];
        float rn = rsqrtf(x * x + y * y + z * z);
        x *= rn; y *= rn; z *= rn;
        const float s3 = 1.7320508075688772f;
        const float s5 = 2.2360679774997896f;
        float* o = g_shb + (size_t)e * 8;
        o[0] = s3 * x;
        o[1] = s3 * y;
        o[2] = s3 * z;
        o[3] = s5 * s3 * x * z;
        o[4] = s5 * s3 * x * y;
        o[5] = s5 * (y * y - 0.5f * (x * x + z * z));
        o[6] = s5 * s3 * y * z;
        o[7] = s5 * (s3 * 0.5f) * (z * z - x * x);
    }
    for (int i = tid; i < Nn * 128; i += gs) g_h1[i] = 0.0f;
    for (int i = tid; i < Nn * 64;  i += gs) g_h2[i] = 0.0f;
    for (int i = tid; i < Nn;       i += gs) g_cnt[i] = 0.0f;
    if (tid < 64) { g_mu[tid] = 0.0f; g_var[tid] = 0.0f; }
}

// ======================= unified fp16 MMA GEMM ===============================
// Out[M, Ntot] = epi(A[M, K=KS*16] @ WT^T + bias). 256 thr, 64 rows/CTA.
// USEZ: blockIdx.z selects (WT,bias,Out) pair (for merged u1/u2).
template <int KS, int NT, int ACT, int OUTH, int MINB, int USEZ>
__global__ void __launch_bounds__(256, MINB) mma_gemm(
    const float* __restrict__ Af,
    const __half* __restrict__ WTa, const __half* __restrict__ WTb,
    const float* __restrict__ biasa, const float* __restrict__ biasb,
    void* __restrict__ Outa, void* __restrict__ Outb,
    int M, int Ntot)
{
    constexpr int K = KS * 16;
    constexpr int CTAN = NT * 16;
    constexpr int ROWW = KS * 8;
    extern __shared__ __align__(16) char ws[];
    const int tid = threadIdx.x;
    const int wid = tid >> 5, lane = tid & 31;
    const int mt = wid >> 1, nh = wid & 1;
    const int lq = lane >> 2, la = lane & 3;
    const int bn0 = blockIdx.y * CTAN;
    const __half* WT = (USEZ && blockIdx.z) ? WTb : WTa;
    const float* bias = (USEZ && blockIdx.z) ? biasb : biasa;
    void* Outv = (USEZ && blockIdx.z) ? Outb : Outa;

    for (int idx = tid; idx < CTAN * KS * 2; idx += 256) {
        int row = idx / (KS * 2);
        int q   = idx - row * (KS * 2);
        const __half* src = WT + (size_t)(bn0 + row) * K + q * 8;
        uint32_t dst = smem_u32(ws + row * (KS * 32) + ((q ^ (row & 7)) * 16));
        CP_ASYNC16(dst, src);
    }
    CP_COMMIT();

    const int r0 = blockIdx.x * 64 + mt * 16 + lq;
    const int r1 = r0 + 8;
    const bool v0 = r0 < M, v1 = r1 < M;

    uint32_t A0[KS], A1[KS], A2[KS], A3[KS];
    {
        const float* a0p = Af + (size_t)(v0 ? r0 : 0) * K + 2 * la;
        const float* a1p = Af + (size_t)(v1 ? r1 : 0) * K + 2 * la;
#pragma unroll
        for (int ks = 0; ks < KS; ++ks) {
            float2 f0 = *reinterpret_cast<const float2*>(a0p + ks * 16);
            float2 f2 = *reinterpret_cast<const float2*>(a0p + ks * 16 + 8);
            float2 f1 = *reinterpret_cast<const float2*>(a1p + ks * 16);
            float2 f3 = *reinterpret_cast<const float2*>(a1p + ks * 16 + 8);
            A0[ks] = v0 ? pack_h2(f0.x, f0.y) : 0u;
            A2[ks] = v0 ? pack_h2(f2.x, f2.y) : 0u;
            A1[ks] = v1 ? pack_h2(f1.x, f1.y) : 0u;
            A3[ks] = v1 ? pack_h2(f3.x, f3.y) : 0u;
        }
    }

    float c[NT][4];
#pragma unroll
    for (int nt = 0; nt < NT; ++nt) {
        float2 bb = __ldg(reinterpret_cast<const float2*>(
            bias + bn0 + (nh * NT + nt) * 8 + la * 2));
        c[nt][0] = bb.x; c[nt][1] = bb.y;
        c[nt][2] = bb.x; c[nt][3] = bb.y;
    }

    CP_WAIT0();
    __syncthreads();
    const uint32_t* wb = reinterpret_cast<const uint32_t*>(ws);
#pragma unroll
    for (int ks = 0; ks < KS; ++ks) {
#pragma unroll
        for (int nt = 0; nt < NT; ++nt) {
            const int base = ((nh * NT + nt) * 8 + lq) * ROWW;
            uint32_t b0 = wb[base + (((2 * ks)     ^ lq) * 4) + la];
            uint32_t b1 = wb[base + (((2 * ks + 1) ^ lq) * 4) + la];
            mma_f16_m16n8k16(c[nt], A0[ks], A1[ks], A2[ks], A3[ks], b0, b1);
        }
    }

#pragma unroll
    for (int nt = 0; nt < NT; ++nt) {
        const int gcol = bn0 + (nh * NT + nt) * 8 + la * 2;
#pragma unroll
        for (int e = 0; e < 2; ++e) {
            int r = e ? r1 : r0;
            if (e ? !v1 : !v0) continue;
            float x0 = c[nt][e * 2], x1 = c[nt][e * 2 + 1];
            if (ACT) { x0 = softplusf(x0); x1 = softplusf(x1); }
            if (OUTH) {
                *reinterpret_cast<__half2*>((__half*)Outv + (size_t)r * Ntot + gcol) =
                    __floats2half2_rn(x0, x1);
            } else {
                *reinterpret_cast<float2*>((float*)Outv + (size_t)r * Ntot + gcol) =
                    make_float2(x0, x1);
            }
        }
    }
}

// ======================= out GEMM with fused BN apply ========================
// out = softplus( softplus(BN(h2)) @ w_out^T + b_out ) + skip.
// A (K=64) built inline: a = softplus((h2-mu)*rs*gamma + beta), fp16.
__global__ void __launch_bounds__(256, 2) out_gemm(
    const __half* __restrict__ WT, const float* __restrict__ bias,
    const float* __restrict__ gamma, const float* __restrict__ beta,
    const float* __restrict__ addsrc, float* __restrict__ Outv,
    int M, int Nn)
{
    constexpr int KS = 4, NT = 8, K = 64, CTAN = 128, ROWW = 32;
    extern __shared__ __align__(16) char ws[];
    const int tid = threadIdx.x;
    const int wid = tid >> 5, lane = tid & 31;
    const int mt = wid >> 1, nh = wid & 1;
    const int lq = lane >> 2, la = lane & 3;
    const int bn0 = blockIdx.y * CTAN;

    for (int idx = tid; idx < CTAN * KS * 2; idx += 256) {
        int row = idx / (KS * 2);
        int q   = idx - row * (KS * 2);
        const __half* src = WT + (size_t)(bn0 + row) * K + q * 8;
        uint32_t dst = smem_u32(ws + row * (KS * 32) + ((q ^ (row & 7)) * 16));
        CP_ASYNC16(dst, src);
    }
    CP_COMMIT();

    const int r0 = blockIdx.x * 64 + mt * 16 + lq;
    const int r1 = r0 + 8;
    const bool v0 = r0 < M, v1 = r1 < M;
    const float invN = 1.0f / (float)Nn;

    uint32_t A0[KS], A1[KS], A2[KS], A3[KS];
#pragma unroll
    for (int ks = 0; ks < KS; ++ks) {
#pragma unroll
        for (int half8 = 0; half8 < 2; ++half8) {
            int col = ks * 16 + 2 * la + half8 * 8;
            float2 mu2 = *reinterpret_cast<const float2*>(g_mu + col);
            float2 vv2 = *reinterpret_cast<const float2*>(g_var + col);
            float2 ga  = __ldg(reinterpret_cast<const float2*>(gamma + col));
            float2 be  = __ldg(reinterpret_cast<const float2*>(beta + col));
            float m0 = mu2.x * invN, m1 = mu2.y * invN;
            float s0 = rsqrtf(vv2.x * invN - m0 * m0 + 1e-5f) * ga.x;
            float s1 = rsqrtf(vv2.y * invN - m1 * m1 + 1e-5f) * ga.y;
            float sh0 = be.x - m0 * s0, sh1 = be.y - m1 * s1;
            uint32_t p0 = 0u, p1 = 0u;
            if (v0) {
                const float* h = g_h2 + (size_t)r0 * 64 + col;
                p0 = pack_h2(softplusf(h[0] * s0 + sh0), softplusf(h[1] * s1 + sh1));
            }
            if (v1) {
                const float* h = g_h2 + (size_t)r1 * 64 + col;
                p1 = pack_h2(softplusf(h[0] * s0 + sh0), softplusf(h[1] * s1 + sh1));
            }
            if (half8 == 0) { A0[ks] = p0; A1[ks] = p1; }
            else            { A2[ks] = p0; A3[ks] = p1; }
        }
    }

    float c[NT][4];
#pragma unroll
    for (int nt = 0; nt < NT; ++nt) {
        float2 bb = __ldg(reinterpret_cast<const float2*>(
            bias + bn0 + (nh * NT + nt) * 8 + la * 2));
        c[nt][0] = bb.x; c[nt][1] = bb.y;
        c[nt][2] = bb.x; c[nt][3] = bb.y;
    }

    CP_WAIT0();
    __syncthreads();
    const uint32_t* wb = reinterpret_cast<const uint32_t*>(ws);
#pragma unroll
    for (int ks = 0; ks < KS; ++ks) {
#pragma unroll
        for (int nt = 0; nt < NT; ++nt) {
            const int base = ((nh * NT + nt) * 8 + lq) * ROWW;
            uint32_t b0 = wb[base + (((2 * ks)     ^ lq) * 4) + la];
            uint32_t b1 = wb[base + (((2 * ks + 1) ^ lq) * 4) + la];
            mma_f16_m16n8k16(c[nt], A0[ks], A1[ks], A2[ks], A3[ks], b0, b1);
        }
    }

#pragma unroll
    for (int nt = 0; nt < NT; ++nt) {
        const int gcol = bn0 + (nh * NT + nt) * 8 + la * 2;
#pragma unroll
        for (int e = 0; e < 2; ++e) {
            int r = e ? r1 : r0;
            if (e ? !v1 : !v0) continue;
            float x0 = softplusf(c[nt][e * 2]);
            float x1 = softplusf(c[nt][e * 2 + 1]);
            float2 ad = *reinterpret_cast<const float2*>(
                addsrc + (size_t)r * 256 + gcol);
            *reinterpret_cast<float2*>(Outv + (size_t)r * 256 + gcol) =
                make_float2(x0 + ad.x, x1 + ad.y);
        }
    }
}

// ======================= fp16 mma.sync fused message pass ====================
// (unchanged — proven config)
#define EBLK     96
#define NTHR     384
#define OFF_W0   0
#define OFF_W1   65536
#define OFF_SS   131072
#define OFF_BIAS 162176
#define SMEM_MSG_B 182656

__device__ __forceinline__ void fill_W4_async(char* smem, uint32_t bufoff,
    const __half* __restrict__ WT, int ch0, int tid)
{
    for (int idx = tid; idx < 4096; idx += NTHR) {
        int sub = idx >> 10;
        int w   = idx & 1023;
        int row = w >> 4;
        int q   = w & 15;
        const __half* src = WT + ((size_t)(ch0 + sub) * 64 + row) * 128 + q * 8;
        uint32_t dst = smem_u32(smem + bufoff + sub * 16384 +
                                row * 256 + ((q ^ (row & 7)) * 16));
        CP_ASYNC16(dst, src);
    }
}

template <int PASS>
__global__ void __launch_bounds__(NTHR, 1) msg_mma_kernel(
    const int* __restrict__ ei, const __half* __restrict__ Uh,
    const __half* __restrict__ WT, const float* __restrict__ B2, int E)
{
    extern __shared__ __align__(16) char smem[];
    float* sS    = reinterpret_cast<float*>(smem + OFF_SS);     // [96][81]
    float* sBias = reinterpret_cast<float*>(smem + OFF_BIAS);   // [5120]

    const int tid = threadIdx.x;
    const int wid = tid >> 5, lane = tid & 31;
    const int mt = wid >> 1, nh = wid & 1;
    const int lq = lane >> 2, la = lane & 3;
    const int e0 = blockIdx.x * EBLK;
    const int ne = min(EBLK, E - e0);
    const int r0 = mt * 16 + lq, r1 = r0 + 8;
    const bool v0 = r0 < ne, v1 = r1 < ne;

    fill_W4_async(smem, OFF_W0, WT, 0, tid);
    CP_COMMIT();

    for (int i = tid; i < 5120; i += NTHR) sBias[i] = B2[i];

    if (PASS == 1) {
        for (int idx = tid; idx < EBLK * 64; idx += NTHR) {
            int e = idx >> 6, i = idx & 63;
            float v = 0.0f;
            if (e < ne) {
                int dst = ei[E + e0 + e];
                v = g_h[(size_t)dst * 64 + i];
            }
            sS[e * 81 + i] = v;
        }
    } else {
        for (int idx = tid; idx < EBLK * 80; idx += NTHR) {
            int e = idx / 80, j = idx - e * 80;
            float v = 0.0f;
            if (e < ne) {
                int dst = ei[E + e0 + e];
                float rc = 1.0f / fmaxf(g_cnt[dst], 1.0f);
                const float* he = g_h1 + (size_t)dst * 128;
                if (j < 64) {
                    v = he[j] * rc + g_h[(size_t)dst * 64 + j];
                } else if (j < 72) {
                    int i = j - 64; float p = 0.0f;
#pragma unroll
                    for (int m = 0; m < 3; ++m)
                        p += he[64 + i * 3 + m] * g_shb[(size_t)(e0 + e) * 8 + m];
                    v = p * rc * 0.5773502691896258f;
                } else {
                    int i = j - 72; float p = 0.0f;
#pragma unroll
                    for (int m = 0; m < 5; ++m)
                        p += he[88 + i * 5 + m] * g_shb[(size_t)(e0 + e) * 8 + 3 + m];
                    v = p * rc * 0.4472135954999579f;
                }
            }
            sS[e * 81 + j] = v;
        }
    }

    uint32_t A0[8], A1[8], A2[8], A3[8];
    {
        const uint32_t* u0 = reinterpret_cast<const uint32_t*>(
            Uh + (size_t)(e0 + (v0 ? r0 : 0)) * 128) + la;
        const uint32_t* u1 = reinterpret_cast<const uint32_t*>(
            Uh + (size_t)(e0 + (v1 ? r1 : 0)) * 128) + la;
#pragma unroll
        for (int ks = 0; ks < 8; ++ks) {
            A0[ks] = v0 ? u0[ks * 8]     : 0u;
            A2[ks] = v0 ? u0[ks * 8 + 4] : 0u;
            A1[ks] = v1 ? u1[ks * 8]     : 0u;
            A3[ks] = v1 ? u1[ks * 8 + 4] : 0u;
        }
    }

    float accA[4][4];
    float accB[4], accC[4];
#pragma unroll
    for (int i = 0; i < 4; ++i) {
#pragma unroll
        for (int j = 0; j < 4; ++j) accA[i][j] = 0.0f;
        accB[i] = 0.0f; accC[i] = 0.0f;
    }

    CP_WAIT0();
    __syncthreads();

    for (int qd = 0; qd < 20; ++qd) {
        const char* cur = smem + ((qd & 1) ? OFF_W1 : OFF_W0);
        if (qd + 1 < 20) {
            fill_W4_async(smem, (qd & 1) ? OFF_W0 : OFF_W1, WT, 4 * (qd + 1), tid);
            CP_COMMIT();
        }

#pragma unroll
        for (int sub = 0; sub < 4; ++sub) {
            const int ch = 4 * qd + sub;
            const uint32_t* wb = reinterpret_cast<const uint32_t*>(cur + sub * 16384);

            float c[4][4];
#pragma unroll
            for (int ntl = 0; ntl < 4; ++ntl) {
                const float2 bb = *reinterpret_cast<const float2*>(
                    sBias + ch * 64 + (nh * 4 + ntl) * 8 + la * 2);
                c[ntl][0] = bb.x; c[ntl][1] = bb.y;
                c[ntl][2] = bb.x; c[ntl][3] = bb.y;
            }

            uint32_t bcur[4][2], bnxt[4][2];
#pragma unroll
            for (int ntl = 0; ntl < 4; ++ntl) {
                const int base = ((nh * 4 + ntl) * 8 + lq) * 64;
                bcur[ntl][0] = wb[base + (((0) ^ lq) * 4) + la];
                bcur[ntl][1] = wb[base + (((1) ^ lq) * 4) + la];
            }
#pragma unroll
            for (int ks = 0; ks < 8; ++ks) {
                if (ks < 7) {
#pragma unroll
                    for (int ntl = 0; ntl < 4; ++ntl) {
                        const int base = ((nh * 4 + ntl) * 8 + lq) * 64;
                        bnxt[ntl][0] = wb[base + (((2 * ks + 2) ^ lq) * 4) + la];
                        bnxt[ntl][1] = wb[base + (((2 * ks + 3) ^ lq) * 4) + la];
                    }
                }
#pragma unroll
                for (int ntl = 0; ntl < 4; ++ntl)
                    mma_f16_m16n8k16(c[ntl], A0[ks], A1[ks], A2[ks], A3[ks],
                                     bcur[ntl][0], bcur[ntl][1]);
#pragma unroll
                for (int ntl = 0; ntl < 4; ++ntl) {
                    bcur[ntl][0] = bnxt[ntl][0];
                    bcur[ntl][1] = bnxt[ntl][1];
                }
            }

            if (PASS == 2 || ch < 64) {
                float s0 = sS[r0 * 81 + ch];
                float s1 = sS[r1 * 81 + ch];
#pragma unroll
                for (int ntl = 0; ntl < 4; ++ntl) {
                    accA[ntl][0] = fmaf(s0, c[ntl][0], accA[ntl][0]);
                    accA[ntl][1] = fmaf(s0, c[ntl][1], accA[ntl][1]);
                    accA[ntl][2] = fmaf(s1, c[ntl][2], accA[ntl][2]);
                    accA[ntl][3] = fmaf(s1, c[ntl][3], accA[ntl][3]);
                }
            } else if (ch < 72) {
#pragma unroll
                for (int ntl = 0; ntl < 4; ++ntl) {
                    int i = (ch - 64) * 8 + nh * 4 + ntl;
                    float s0 = sS[r0 * 81 + i];
                    float s1 = sS[r1 * 81 + i];
                    accB[0] = fmaf(s0, c[ntl][0], accB[0]);
                    accB[1] = fmaf(s0, c[ntl][1], accB[1]);
                    accB[2] = fmaf(s1, c[ntl][2], accB[2]);
                    accB[3] = fmaf(s1, c[ntl][3], accB[3]);
                }
            } else {
#pragma unroll
                for (int ntl = 0; ntl < 4; ++ntl) {
                    int i = (ch - 72) * 8 + nh * 4 + ntl;
                    float s0 = sS[r0 * 81 + i];
                    float s1 = sS[r1 * 81 + i];
                    accC[0] = fmaf(s0, c[ntl][0], accC[0]);
                    accC[1] = fmaf(s0, c[ntl][1], accC[1]);
                    accC[2] = fmaf(s1, c[ntl][2], accC[2]);
                    accC[3] = fmaf(s1, c[ntl][3], accC[3]);
                }
            }
        }

        if (qd + 1 < 20) CP_WAIT0();
        __syncthreads();
    }

#pragma unroll
    for (int e = 0; e < 2; ++e) {
        int r = e ? r1 : r0;
        if (r >= ne) continue;
        int src = ei[e0 + r];
        if (PASS == 1) {
            const float C1 = 0.125f;
            float* d1 = g_h1 + (size_t)src * 128;
#pragma unroll
            for (int ntl = 0; ntl < 4; ++ntl) {
                int col = (nh * 4 + ntl) * 8 + la * 2;
                atomicAdd(d1 + col,     C1 * accA[ntl][e * 2]);
                atomicAdd(d1 + col + 1, C1 * accA[ntl][e * 2 + 1]);
            }
            float sh[8];
#pragma unroll
            for (int m = 0; m < 8; ++m) sh[m] = g_shb[(size_t)(e0 + r) * 8 + m];
#pragma unroll
            for (int b = 0; b < 2; ++b) {
                int k = la * 2 + b;
                float a1v = C1 * accB[e * 2 + b];
                float a2v = C1 * accC[e * 2 + b];
#pragma unroll
                for (int m = 0; m < 3; ++m)
                    atomicAdd(d1 + 64 + k * 3 + m, a1v * sh[m]);
#pragma unroll
                for (int m = 0; m < 5; ++m)
                    atomicAdd(d1 + 88 + k * 5 + m, a2v * sh[3 + m]);
            }
            if (nh == 0 && la == 0) atomicAdd(&g_cnt[src], 1.0f);
        } else {
            const float INV = 0.11180339887498948f;  // 1/sqrt(80)
            float* d2 = g_h2 + (size_t)src * 64;
#pragma unroll
            for (int ntl = 0; ntl < 4; ++ntl) {
                int col = (nh * 4 + ntl) * 8 + la * 2;
                atomicAdd(d2 + col,     INV * accA[ntl][e * 2]);
                atomicAdd(d2 + col + 1, INV * accA[ntl][e * 2 + 1]);
            }
        }
    }
}

// ---------------- coalesced h2 finalize + BN reduce --------------------------
__global__ void __launch_bounds__(256) bn_reduce_kernel(int Nn)
{
    __shared__ float ss[4][64], ss2[4][64];
    const int c = threadIdx.x & 63, g = threadIdx.x >> 6;
    float s = 0.0f, s2 = 0.0f;
    for (int base = blockIdx.x * 4; base < Nn; base += gridDim.x * 4) {
        int n = base + g;
        if (n < Nn) {
            float x = g_h2[(size_t)n * 64 + c] / fmaxf(g_cnt[n], 1.0f);
            g_h2[(size_t)n * 64 + c] = x;
            s += x; s2 += x * x;
        }
    }
    ss[g][c] = s; ss2[g][c] = s2;
    __syncthreads();
    if (g == 0) {
        float ts = ss[0][c] + ss[1][c] + ss[2][c] + ss[3][c];
        float ts2 = ss2[0][c] + ss2[1][c] + ss2[2][c] + ss2[3][c];
        atomicAdd(&g_mu[c], ts);
        atomicAdd(&g_var[c], ts2);
    }
}

// ---------------- launch ----------------------------------------------------
extern "C" void kernel_launch(void* const* d_in, const int* in_sizes, int n_in,
                              void* d_out, int out_size)
{
    const float* node_feature = (const float*)d_in[0];
    const int*   edge_index   = (const int*)d_in[1];
    const float* edge_feature = (const float*)d_in[2];
    const float* edge_vec     = (const float*)d_in[3];
    const float* w_node = (const float*)d_in[4];
    const float* b_node = (const float*)d_in[5];
    const float* w_skip = (const float*)d_in[6];
    const float* b_skip = (const float*)d_in[7];
    const float* fc1_w1 = (const float*)d_in[8];
    const float* fc1_b1 = (const float*)d_in[9];
    const float* fc1_w2 = (const float*)d_in[10];
    const float* fc1_b2 = (const float*)d_in[11];
    const float* fc2_w1 = (const float*)d_in[12];
    const float* fc2_b1 = (const float*)d_in[13];
    const float* fc2_w2 = (const float*)d_in[14];
    const float* fc2_b2 = (const float*)d_in[15];
    const float* bn_gamma = (const float*)d_in[16];
    const float* bn_beta  = (const float*)d_in[17];
    const float* w_out = (const float*)d_in[18];
    const float* b_out = (const float*)d_in[19];
    float* out = (float*)d_out;

    const int Nn = in_sizes[0] / 256;   // 10000
    const int E  = in_sizes[2] / 128;   // 40000

    float *p_skip, *p_h;
    __half *p_u1h, *p_u2h, *p_w1t, *p_w2t, *p_wt1a, *p_wt1b;
    __half *p_wskt, *p_wndt, *p_wott;
    cudaGetSymbolAddress((void**)&p_skip, g_skip);
    cudaGetSymbolAddress((void**)&p_h,    g_h);
    cudaGetSymbolAddress((void**)&p_u1h,  g_u1h);
    cudaGetSymbolAddress((void**)&p_u2h,  g_u2h);
    cudaGetSymbolAddress((void**)&p_w1t,  g_w1t);
    cudaGetSymbolAddress((void**)&p_w2t,  g_w2t);
    cudaGetSymbolAddress((void**)&p_wt1a, g_wt1a);
    cudaGetSymbolAddress((void**)&p_wt1b, g_wt1b);
    cudaGetSymbolAddress((void**)&p_wskt, g_wskt);
    cudaGetSymbolAddress((void**)&p_wndt, g_wndt);
    cudaGetSymbolAddress((void**)&p_wott, g_wott);

    cudaFuncSetAttribute((const void*)msg_mma_kernel<1>,
                         cudaFuncAttributeMaxDynamicSharedMemorySize, SMEM_MSG_B);
    cudaFuncSetAttribute((const void*)msg_mma_kernel<2>,
                         cudaFuncAttributeMaxDynamicSharedMemorySize, SMEM_MSG_B);
    cudaFuncSetAttribute((const void*)mma_gemm<16, 8, 0, 0, 1, 0>,
                         cudaFuncAttributeMaxDynamicSharedMemorySize, 65536);
    cudaFuncSetAttribute((const void*)mma_gemm<16, 4, 0, 0, 1, 0>,
                         cudaFuncAttributeMaxDynamicSharedMemorySize, 32768);
    cudaFuncSetAttribute((const void*)mma_gemm<8, 8, 1, 1, 2, 1>,
                         cudaFuncAttributeMaxDynamicSharedMemorySize, 32768);
    cudaFuncSetAttribute((const void*)out_gemm,
                         cudaFuncAttributeMaxDynamicSharedMemorySize, 16384);

    // one launch: all weight transposes + sph harmonics + zero buffers
    megaprep_kernel<<<1536, 256>>>(edge_vec, E, Nn,
        fc1_w2, fc2_w2, fc1_w1, fc2_w1, w_skip, w_node, w_out);

    const int mblk = (Nn + 63) / 64;   // 157
    const int ublk = (E + 63) / 64;    // 625

    // skip = node @ w_skip + b  (K=256, N=256)
    mma_gemm<16, 8, 0, 0, 1, 0><<<dim3(mblk, 2), 256, 65536>>>(
        node_feature, p_wskt, nullptr, b_skip, nullptr, p_skip, nullptr, Nn, 256);
    // h = node @ w_node + b     (K=256, N=64)
    mma_gemm<16, 4, 0, 0, 1, 0><<<dim3(mblk, 1), 256, 32768>>>(
        node_feature, p_wndt, nullptr, b_node, nullptr, p_h, nullptr, Nn, 64);
    // u1 & u2 in ONE launch: z selects weights/bias/output (K=128, N=128)
    mma_gemm<8, 8, 1, 1, 2, 1><<<dim3(ublk, 1, 2), 256, 32768>>>(
        edge_feature, p_wt1a, p_wt1b, fc1_b1, fc2_b1, p_u1h, p_u2h, E, 128);

    const int nblk = (E + EBLK - 1) / EBLK;
    msg_mma_kernel<1><<<nblk, NTHR, SMEM_MSG_B>>>(edge_index, p_u1h, p_w1t, fc1_b2, E);
    msg_mma_kernel<2><<<nblk, NTHR, SMEM_MSG_B>>>(edge_index, p_u2h, p_w2t, fc2_b2, E);

    bn_reduce_kernel<<<148, 256>>>(Nn);

    // out = softplus(softplus(BN(h2)) @ w_out + b_out) + skip (BN fused in A)
    out_gemm<<<dim3(mblk, 2), 256, 16384>>>(
        p_wott, b_out, bn_gamma, bn_beta, p_skip, out, Nn, Nn);
}